// round 3
// baseline (speedup 1.0000x reference)
#include <cuda_runtime.h>
#include <math.h>

#define BB 4
#define SS 2048
#define DD 1024
#define GG 512
#define WW 8
#define SDIFF 2047              // diffs per batch
#define ND (BB*SDIFF)           // 8188 total diff rows
#define MT 16                   // diff rows per CTA in main kernel
#define NTILES ((ND + MT - 1)/MT)   // 512
#define WSTRIDE 18              // s_wT row stride (floats): 8B-aligned pairs, <=2-way conflict

// packed f32x2 helpers
#define FMA_F32X2(d, a, b) \
    asm("fma.rn.f32x2 %0, %1, %2, %0;" : "+l"(d) : "l"(a), "l"(b))

__device__ __forceinline__ unsigned long long pack2(float lo, float hi) {
    unsigned long long r;
    asm("mov.b64 %0, {%1, %2};" : "=l"(r) : "f"(lo), "f"(hi));
    return r;
}
__device__ __forceinline__ float2 unpack2(unsigned long long v) {
    float2 r;
    asm("mov.b64 {%0, %1}, %2;" : "=f"(r.x), "=f"(r.y) : "l"(v));
    return r;
}

// Scratch (static __device__ — no allocations allowed)
__device__ float d_ginv[GG];
__device__ unsigned long long d_gTp[(DD/2)*GG];  // [kp][g] = (gT[2kp][g], gT[2kp+1][g]) / ||g||
__device__ float d_mw[ND];                        // tanh(2*mag) per diff
__device__ float d_blended[8388608];              // [ND][DD]

// ---------------- kernel 0a: inverse guidance norms ----------------
__global__ void k_ginv(const float* __restrict__ guid) {
    int g = blockIdx.x;
    const float4* row = (const float4*)(guid + (size_t)g * DD);
    float4 x = row[threadIdx.x];
    float s = x.x*x.x + x.y*x.y + x.z*x.z + x.w*x.w;
    #pragma unroll
    for (int o = 16; o; o >>= 1) s += __shfl_xor_sync(0xffffffffu, s, o);
    __shared__ float red[8];
    int wid = threadIdx.x >> 5, lane = threadIdx.x & 31;
    if (lane == 0) red[wid] = s;
    __syncthreads();
    if (threadIdx.x == 0) {
        float t = 0.f;
        #pragma unroll
        for (int i = 0; i < 8; i++) t += red[i];
        d_ginv[g] = 1.0f / fmaxf(sqrtf(t), 1e-8f);
    }
}

// ---------------- kernel 0b: build k-paired, norm-folded transposed guidance ----------------
__global__ void k_gtp(const float* __restrict__ guid) {
    int g = blockIdx.x;
    float inv = d_ginv[g];
    const float2* row = (const float2*)(guid + (size_t)g * DD);
    for (int kp = threadIdx.x; kp < DD/2; kp += 256) {
        float2 v = row[kp];
        d_gTp[(size_t)kp * GG + g] = pack2(v.x * inv, v.y * inv);
    }
}

// ---------------- kernel 1: per-diff normalize -> sims -> softmax -> influence -> blended ----------------
__global__ void __launch_bounds__(256, 2) k_main(
        const float* __restrict__ emb, const float* __restrict__ guid) {
    extern __shared__ float sm[];
    float* s_normed = sm;            // [MT][DD]          64KB
    float* s_wT     = sm + MT * DD;  // [GG][WSTRIDE]     36KB (weights transposed: [g][m])
    int tid  = threadIdx.x;
    int lane = tid & 31, wid = tid >> 5;
    int tile = blockIdx.x;

    // ---- Phase 1: diffs, magnitude, normalize into shared ----
    #pragma unroll
    for (int mm = 0; mm < 2; mm++) {
        int m = wid + 8 * mm;
        int r = tile * MT + m;
        float4 df[8];
        float ssq = 0.f;
        if (r < ND) {
            int b = r / SDIFF;
            int i = r - b * SDIFF;
            const float4* e0 = (const float4*)(emb + ((size_t)b * SS + i) * DD);
            #pragma unroll
            for (int it = 0; it < 8; it++) {
                int v = lane + 32 * it;
                float4 a = e0[v + DD/4];
                float4 c = e0[v];
                df[it].x = a.x - c.x; df[it].y = a.y - c.y;
                df[it].z = a.z - c.z; df[it].w = a.w - c.w;
                ssq += df[it].x*df[it].x + df[it].y*df[it].y
                     + df[it].z*df[it].z + df[it].w*df[it].w;
            }
        } else {
            #pragma unroll
            for (int it = 0; it < 8; it++) df[it] = make_float4(0.f,0.f,0.f,0.f);
        }
        #pragma unroll
        for (int o = 16; o; o >>= 1) ssq += __shfl_xor_sync(0xffffffffu, ssq, o);
        float mag = sqrtf(ssq);
        float scale = (mag > 1e-6f) ? (1.0f / mag) : 0.0f;
        if (r < ND && lane == 0) d_mw[r] = tanhf(2.0f * mag);
        float4* srow = (float4*)(s_normed + m * DD);
        #pragma unroll
        for (int it = 0; it < 8; it++) {
            float4 o4;
            o4.x = df[it].x * scale; o4.y = df[it].y * scale;
            o4.z = df[it].z * scale; o4.w = df[it].w * scale;
            srow[lane + 32 * it] = o4;
        }
    }
    __syncthreads();

    // ---- Phase 2: sims[g][m] = normed[m] . gT[:,g], packed over k-pairs ----
    {
        unsigned long long acc[MT][2];
        #pragma unroll
        for (int m = 0; m < MT; m++) { acc[m][0] = 0ull; acc[m][1] = 0ull; }
        int g0 = tid, g1 = tid + 256;
        #pragma unroll 1
        for (int kp = 0; kp < DD/2; kp += 2) {
            unsigned long long a0 = d_gTp[(size_t)kp * GG + g0];
            unsigned long long a1 = d_gTp[(size_t)kp * GG + g1];
            unsigned long long b0 = d_gTp[(size_t)(kp+1) * GG + g0];
            unsigned long long b1 = d_gTp[(size_t)(kp+1) * GG + g1];
            #pragma unroll
            for (int m = 0; m < MT; m++) {
                ulonglong2 nm = *(const ulonglong2*)(s_normed + m * DD + 2 * kp);
                FMA_F32X2(acc[m][0], nm.x, a0);
                FMA_F32X2(acc[m][1], nm.x, a1);
                FMA_F32X2(acc[m][0], nm.y, b0);
                FMA_F32X2(acc[m][1], nm.y, b1);
            }
        }
        #pragma unroll
        for (int m = 0; m < MT; m++) {
            float2 u0 = unpack2(acc[m][0]);
            float2 u1 = unpack2(acc[m][1]);
            s_wT[g0 * WSTRIDE + m] = u0.x + u0.y;
            s_wT[g1 * WSTRIDE + m] = u1.x + u1.y;
        }
    }
    __syncthreads();

    // ---- Phase 3: softmax over g (temperature 2), one warp per 2 rows ----
    #pragma unroll
    for (int mm = 0; mm < 2; mm++) {
        int m = wid + 8 * mm;
        float mx = -1e30f;
        for (int j = lane; j < GG; j += 32) mx = fmaxf(mx, s_wT[j * WSTRIDE + m]);
        #pragma unroll
        for (int o = 16; o; o >>= 1) mx = fmaxf(mx, __shfl_xor_sync(0xffffffffu, mx, o));
        float sum = 0.f;
        for (int j = lane; j < GG; j += 32) {
            float e = expf(2.0f * (s_wT[j * WSTRIDE + m] - mx));
            s_wT[j * WSTRIDE + m] = e;
            sum += e;
        }
        #pragma unroll
        for (int o = 16; o; o >>= 1) sum += __shfl_xor_sync(0xffffffffu, sum, o);
        float inv = 1.0f / sum;
        for (int j = lane; j < GG; j += 32) s_wT[j * WSTRIDE + m] *= inv;
    }
    __syncthreads();

    // ---- Phase 4: influence[m][d] = sum_g w[m][g]*guid[g][d], packed over m-pairs ----
    {
        unsigned long long fa[MT/2][4];   // [m-pair][d within thread's 4]
        #pragma unroll
        for (int mp = 0; mp < MT/2; mp++) {
            fa[mp][0] = 0ull; fa[mp][1] = 0ull; fa[mp][2] = 0ull; fa[mp][3] = 0ull;
        }
        const float4* gp4 = (const float4*)guid;   // thread owns d = 4*tid .. 4*tid+3
        #pragma unroll 1
        for (int g = 0; g < GG; g++) {
            float4 gv = gp4[(size_t)g * (DD/4) + tid];
            unsigned long long px = pack2(gv.x, gv.x);
            unsigned long long py = pack2(gv.y, gv.y);
            unsigned long long pz = pack2(gv.z, gv.z);
            unsigned long long pw = pack2(gv.w, gv.w);
            const float* wrow = s_wT + g * WSTRIDE;
            #pragma unroll
            for (int mp = 0; mp < MT/2; mp++) {
                unsigned long long wp = *(const unsigned long long*)(wrow + 2 * mp);
                FMA_F32X2(fa[mp][0], wp, px);
                FMA_F32X2(fa[mp][1], wp, py);
                FMA_F32X2(fa[mp][2], wp, pz);
                FMA_F32X2(fa[mp][3], wp, pw);
            }
        }
        int d0 = tid * 4;
        #pragma unroll
        for (int mp = 0; mp < MT/2; mp++) {
            float2 f0 = unpack2(fa[mp][0]);
            float2 f1 = unpack2(fa[mp][1]);
            float2 f2 = unpack2(fa[mp][2]);
            float2 f3 = unpack2(fa[mp][3]);
            int m0 = 2 * mp, m1 = 2 * mp + 1;
            int r0 = tile * MT + m0, r1 = tile * MT + m1;
            if (r0 < ND) {
                float4 nm = *(const float4*)(s_normed + m0 * DD + d0);
                float4 o;
                o.x = 0.6f * nm.x + 0.4f * f0.x;
                o.y = 0.6f * nm.y + 0.4f * f1.x;
                o.z = 0.6f * nm.z + 0.4f * f2.x;
                o.w = 0.6f * nm.w + 0.4f * f3.x;
                *(float4*)(d_blended + (size_t)r0 * DD + d0) = o;
            }
            if (r1 < ND) {
                float4 nm = *(const float4*)(s_normed + m1 * DD + d0);
                float4 o;
                o.x = 0.6f * nm.x + 0.4f * f0.y;
                o.y = 0.6f * nm.y + 0.4f * f1.y;
                o.z = 0.6f * nm.z + 0.4f * f2.y;
                o.w = 0.6f * nm.w + 0.4f * f3.y;
                *(float4*)(d_blended + (size_t)r1 * DD + d0) = o;
            }
        }
    }
}

// ---------------- kernel 2: windowed weighted blend into output ----------------
__global__ void __launch_bounds__(256) k_out(float* __restrict__ out) {
    int pos = blockIdx.x;            // 0 .. B*S-1
    int b = pos >> 11;               // / 2048
    int p = pos & (SS - 1);
    int base = b * SDIFF;
    float c[WW];
    float wsum = 0.f;
    #pragma unroll
    for (int k = 0; k < WW; k++) {
        int idx = p - WW + k;
        float ck = 0.f;
        if (p >= 1 && idx >= 0) {
            int w = (p < WW) ? p : WW;
            int j = k - (WW - w);
            float lin = (w > 1) ? (0.1f + 0.9f * (float)j / (float)(w - 1)) : 0.1f;
            ck = lin * d_mw[base + idx];
        }
        c[k] = ck;
        wsum += ck;
    }
    float inv = 1.0f / fmaxf(wsum, 1e-8f);
    int d4 = threadIdx.x;            // float4 index, 256 per row
    float4 o = make_float4(0.f, 0.f, 0.f, 0.f);
    #pragma unroll
    for (int k = 0; k < WW; k++) {
        int idx = p - WW + k;
        if (c[k] != 0.f) {
            float4 v = *(const float4*)(d_blended + (size_t)(base + idx) * DD + d4 * 4);
            o.x = fmaf(c[k], v.x, o.x);
            o.y = fmaf(c[k], v.y, o.y);
            o.z = fmaf(c[k], v.z, o.z);
            o.w = fmaf(c[k], v.w, o.w);
        }
    }
    o.x *= inv; o.y *= inv; o.z *= inv; o.w *= inv;
    ((float4*)out)[(size_t)pos * (DD/4) + d4] = o;
}

extern "C" void kernel_launch(void* const* d_in, const int* in_sizes, int n_in,
                              void* d_out, int out_size) {
    (void)in_sizes; (void)n_in; (void)out_size;
    const float* emb  = (const float*)d_in[0];   // (4, 2048, 1024) f32
    const float* guid = (const float*)d_in[1];   // (512, 1024)     f32
    float* out = (float*)d_out;                  // (4, 2048, 1024) f32

    const int smem = (MT * DD + GG * WSTRIDE) * (int)sizeof(float);  // 102400
    cudaFuncSetAttribute(k_main, cudaFuncAttributeMaxDynamicSharedMemorySize, smem);

    k_ginv<<<GG, 256>>>(guid);
    k_gtp<<<GG, 256>>>(guid);
    k_main<<<NTILES, 256, smem>>>(emb, guid);
    k_out<<<BB * SS, 256>>>(out);
}

// round 6
// speedup vs baseline: 1.8713x; 1.8713x over previous
#include <cuda_runtime.h>
#include <cuda_bf16.h>
#include <mma.h>
#include <cstdint>
#include <math.h>

using namespace nvcuda;

#define BB 4
#define SS 2048
#define DD 1024
#define GG 512
#define WW 8
#define SDIFF 2047
#define ND (BB*SDIFF)            // 8188
#define MPAD 8192

#define LDA 72                   // mm1 smem bf16 tile stride (elems)
#define LDA2 36                  // mm2 smem f32 A stride (elems)
#define LDB2 132                 // mm2 smem f32 B stride (elems)
#define LDC 132                  // f32 epilogue tile stride (elems)
#define SMEM_MM 67584            // 128*132*4 (epilogue reuse dominates)

// ---------------- global scratch ----------------
__device__ float          d_ginv[GG];
__device__ __nv_bfloat16  d_gbf[GG * DD];             // guid/||g|| bf16 [g][k]
__device__ __nv_bfloat16  d_nbf[MPAD * DD];           // normed bf16 [r][k]
__device__ float          d_normf[(size_t)MPAD * DD]; // normed f32
__device__ float          d_mw[MPAD];                 // tanh(2*mag)
__device__ float          d_wexp[(size_t)MPAD * GG];  // exp(2*sims) f32 [r][g]
__device__ float          d_sums[MPAD];               // row sums of exp
__device__ float          d_blended[(size_t)MPAD * DD];

// ---------------- guidance norms ----------------
__global__ void k_ginv(const float* __restrict__ guid) {
    int g = blockIdx.x;
    const float4* row = (const float4*)(guid + (size_t)g * DD);
    float4 x = row[threadIdx.x];
    float s = x.x*x.x + x.y*x.y + x.z*x.z + x.w*x.w;
    #pragma unroll
    for (int o = 16; o; o >>= 1) s += __shfl_xor_sync(0xffffffffu, s, o);
    __shared__ float red[8];
    int w = threadIdx.x >> 5, lane = threadIdx.x & 31;
    if (lane == 0) red[w] = s;
    __syncthreads();
    if (threadIdx.x == 0) {
        float t = 0.f;
        #pragma unroll
        for (int i = 0; i < 8; i++) t += red[i];
        d_ginv[g] = 1.0f / fmaxf(sqrtf(t), 1e-8f);
    }
}

// ---------------- bf16 normalized guidance ----------------
__global__ void k_gbf(const float* __restrict__ guid) {
    int g = blockIdx.x;
    float inv = d_ginv[g];
    const float2* row = (const float2*)(guid + (size_t)g * DD);
    __nv_bfloat162* o1 = (__nv_bfloat162*)(d_gbf + (size_t)g * DD);
    for (int kp = threadIdx.x; kp < DD/2; kp += 256) {
        float2 v = row[kp];
        __nv_bfloat162 hn;
        hn.x = __float2bfloat16(v.x * inv); hn.y = __float2bfloat16(v.y * inv);
        o1[kp] = hn;
    }
}

// ---------------- diffs -> normed (bf16 + f32), mags, zero sums ----------------
__global__ void __launch_bounds__(256) k_prep(const float* __restrict__ emb) {
    int lane = threadIdx.x & 31, wid = threadIdx.x >> 5;
    int r = blockIdx.x * 8 + wid;
    if (lane == 0) d_sums[r] = 0.f;
    __nv_bfloat162* nb = (__nv_bfloat162*)(d_nbf + (size_t)r * DD);
    float4* nf = (float4*)(d_normf + (size_t)r * DD);
    if (r >= ND) {
        __nv_bfloat162 z; z.x = __float2bfloat16(0.f); z.y = z.x;
        #pragma unroll
        for (int it = 0; it < 8; it++) {
            int v = lane + 32 * it;
            nb[2*v] = z; nb[2*v+1] = z;
            nf[v] = make_float4(0.f, 0.f, 0.f, 0.f);
        }
        return;
    }
    int b = r / SDIFF;
    int i = r - b * SDIFF;
    const float4* e0 = (const float4*)(emb + ((size_t)b * SS + i) * DD);
    float4 df[8];
    float ssq = 0.f;
    #pragma unroll
    for (int it = 0; it < 8; it++) {
        int v = lane + 32 * it;
        float4 a = e0[v + DD/4];
        float4 c = e0[v];
        df[it].x = a.x - c.x; df[it].y = a.y - c.y;
        df[it].z = a.z - c.z; df[it].w = a.w - c.w;
        ssq += df[it].x*df[it].x + df[it].y*df[it].y + df[it].z*df[it].z + df[it].w*df[it].w;
    }
    #pragma unroll
    for (int o = 16; o; o >>= 1) ssq += __shfl_xor_sync(0xffffffffu, ssq, o);
    float mag = sqrtf(ssq);
    float scale = (mag > 1e-6f) ? (1.0f / mag) : 0.0f;
    if (lane == 0) d_mw[r] = tanhf(2.0f * mag);
    #pragma unroll
    for (int it = 0; it < 8; it++) {
        int v = lane + 32 * it;
        float4 o4;
        o4.x = df[it].x * scale; o4.y = df[it].y * scale;
        o4.z = df[it].z * scale; o4.w = df[it].w * scale;
        nf[v] = o4;
        __nv_bfloat162 p0, p1;
        p0.x = __float2bfloat16(o4.x); p0.y = __float2bfloat16(o4.y);
        p1.x = __float2bfloat16(o4.z); p1.y = __float2bfloat16(o4.w);
        nb[2*v] = p0; nb[2*v+1] = p1;
    }
}

// ---------------- mm1: sims = normed x gbf^T (bf16), + exp epilogue (f32 out) ----------------
// grid (64, 4). CTA tile 128m x 128n, K=1024 in 16 chunks of 64.
__global__ void __launch_bounds__(256) k_mm1() {
    extern __shared__ __align__(128) char smem[];
    __nv_bfloat16* As = (__nv_bfloat16*)smem;       // [128][LDA]
    __nv_bfloat16* Bs = As + 128 * LDA;             // [128][LDA]
    float* Cs = (float*)smem;                       // [128][LDC] (reuse)
    int tid = threadIdx.x, wid = tid >> 5;
    int wm = wid >> 1, wn = wid & 1;
    int m0 = blockIdx.x * 128, n0 = blockIdx.y * 128;

    wmma::fragment<wmma::accumulator, 16, 16, 16, float> acc[2][4];
    #pragma unroll
    for (int mi = 0; mi < 2; mi++)
        #pragma unroll
        for (int ni = 0; ni < 4; ni++)
            wmma::fill_fragment(acc[mi][ni], 0.0f);

    const uint4* Ag = (const uint4*)d_nbf;   // row stride 128 uint4
    const uint4* Bg = (const uint4*)d_gbf;

    for (int kc = 0; kc < 16; kc++) {
        __syncthreads();
        #pragma unroll
        for (int i = 0; i < 4; i++) {
            int q = tid + i * 256;
            int r = q >> 3, v = q & 7;
            uint4 a = Ag[(size_t)(m0 + r) * 128 + kc * 8 + v];
            *(uint4*)((char*)As + r * (LDA*2) + v * 16) = a;
            uint4 b = Bg[(size_t)(n0 + r) * 128 + kc * 8 + v];
            *(uint4*)((char*)Bs + r * (LDA*2) + v * 16) = b;
        }
        __syncthreads();
        #pragma unroll
        for (int ks = 0; ks < 4; ks++) {
            wmma::fragment<wmma::matrix_a, 16, 16, 16, __nv_bfloat16, wmma::row_major> af[2];
            wmma::fragment<wmma::matrix_b, 16, 16, 16, __nv_bfloat16, wmma::col_major> bf[4];
            #pragma unroll
            for (int mi = 0; mi < 2; mi++)
                wmma::load_matrix_sync(af[mi], As + (wm*32 + mi*16) * LDA + ks*16, LDA);
            #pragma unroll
            for (int ni = 0; ni < 4; ni++)
                wmma::load_matrix_sync(bf[ni], Bs + (wn*64 + ni*16) * LDA + ks*16, LDA);
            #pragma unroll
            for (int mi = 0; mi < 2; mi++)
                #pragma unroll
                for (int ni = 0; ni < 4; ni++)
                    wmma::mma_sync(acc[mi][ni], af[mi], bf[ni], acc[mi][ni]);
        }
    }
    __syncthreads();
    #pragma unroll
    for (int mi = 0; mi < 2; mi++)
        #pragma unroll
        for (int ni = 0; ni < 4; ni++)
            wmma::store_matrix_sync(Cs + (wm*32 + mi*16) * LDC + wn*64 + ni*16,
                                    acc[mi][ni], LDC, wmma::mem_row_major);
    __syncthreads();

    int row = tid >> 1, c0 = (tid & 1) * 64;
    float sum = 0.f;
    float* wout = d_wexp + (size_t)(m0 + row) * GG + n0 + c0;
    #pragma unroll 4
    for (int j = 0; j < 64; j += 4) {
        float4 e;
        e.x = __expf(2.0f * Cs[row * LDC + c0 + j + 0]);
        e.y = __expf(2.0f * Cs[row * LDC + c0 + j + 1]);
        e.z = __expf(2.0f * Cs[row * LDC + c0 + j + 2]);
        e.w = __expf(2.0f * Cs[row * LDC + c0 + j + 3]);
        sum += e.x + e.y + e.z + e.w;
        *(float4*)(wout + j) = e;
    }
    atomicAdd(&d_sums[m0 + row], sum);
}

// ---------------- mm2: influence = wexp x guid (tf32), + blend epilogue ----------------
// grid (64, 8). CTA tile 128m x 128d, K=512 in 16 chunks of 32.
__global__ void __launch_bounds__(256) k_mm2(const float* __restrict__ guid) {
    extern __shared__ __align__(128) char smem[];
    float* As = (float*)smem;                       // [128][LDA2]  18KB
    float* Bs = As + 128 * LDA2;                    // [32][LDB2]   16.9KB
    float* Cs = (float*)smem;                       // [128][LDC] (reuse)
    int tid = threadIdx.x, wid = tid >> 5;
    int wm = wid >> 1, wn = wid & 1;
    int m0 = blockIdx.x * 128, n0 = blockIdx.y * 128;

    wmma::fragment<wmma::accumulator, 16, 16, 8, float> acc[2][4];
    #pragma unroll
    for (int mi = 0; mi < 2; mi++)
        #pragma unroll
        for (int ni = 0; ni < 4; ni++)
            wmma::fill_fragment(acc[mi][ni], 0.0f);

    const float4* Ag = (const float4*)d_wexp;   // row stride 128 float4
    const float4* Bg = (const float4*)guid;     // row stride 256 float4

    for (int kc = 0; kc < 16; kc++) {
        __syncthreads();
        // A chunk: 128 rows x 32 f32
        #pragma unroll
        for (int i = 0; i < 4; i++) {
            int q = tid + i * 256;
            int r = q >> 3, v = q & 7;
            float4 a = Ag[(size_t)(m0 + r) * 128 + kc * 8 + v];
            *(float4*)((char*)As + r * (LDA2*4) + v * 16) = a;
        }
        // B chunk: 32 g-rows x 128 d
        #pragma unroll
        for (int i = 0; i < 4; i++) {
            int q = tid + i * 256;
            int rb = q >> 5, vb = q & 31;
            float4 b = Bg[(size_t)(kc * 32 + rb) * 256 + (n0 >> 2) + vb];
            *(float4*)((char*)Bs + rb * (LDB2*4) + vb * 16) = b;
        }
        __syncthreads();
        #pragma unroll
        for (int ks = 0; ks < 4; ks++) {
            wmma::fragment<wmma::matrix_a, 16, 16, 8, wmma::precision::tf32, wmma::row_major> af[2];
            wmma::fragment<wmma::matrix_b, 16, 16, 8, wmma::precision::tf32, wmma::row_major> bf[4];
            #pragma unroll
            for (int mi = 0; mi < 2; mi++) {
                wmma::load_matrix_sync(af[mi], As + (wm*32 + mi*16) * LDA2 + ks*8, LDA2);
                #pragma unroll
                for (int e = 0; e < af[mi].num_elements; e++)
                    af[mi].x[e] = wmma::__float_to_tf32(af[mi].x[e]);
            }
            #pragma unroll
            for (int ni = 0; ni < 4; ni++) {
                wmma::load_matrix_sync(bf[ni], Bs + (ks*8) * LDB2 + wn*64 + ni*16, LDB2);
                #pragma unroll
                for (int e = 0; e < bf[ni].num_elements; e++)
                    bf[ni].x[e] = wmma::__float_to_tf32(bf[ni].x[e]);
            }
            #pragma unroll
            for (int mi = 0; mi < 2; mi++)
                #pragma unroll
                for (int ni = 0; ni < 4; ni++)
                    wmma::mma_sync(acc[mi][ni], af[mi], bf[ni], acc[mi][ni]);
        }
    }
    __syncthreads();
    #pragma unroll
    for (int mi = 0; mi < 2; mi++)
        #pragma unroll
        for (int ni = 0; ni < 4; ni++)
            wmma::store_matrix_sync(Cs + (wm*32 + mi*16) * LDC + wn*64 + ni*16,
                                    acc[mi][ni], LDC, wmma::mem_row_major);
    __syncthreads();

    int row = tid >> 1, c0 = (tid & 1) * 64;
    int r = m0 + row;
    if (r < ND) {
        float sc = 0.4f / d_sums[r];
        const float4* nf = (const float4*)(d_normf + (size_t)r * DD + n0 + c0);
        float4* ob = (float4*)(d_blended + (size_t)r * DD + n0 + c0);
        #pragma unroll 4
        for (int j = 0; j < 16; j++) {
            float4 c = *(const float4*)&Cs[row * LDC + c0 + j * 4];
            float4 n4 = nf[j];
            float4 o;
            o.x = 0.6f * n4.x + sc * c.x;
            o.y = 0.6f * n4.y + sc * c.y;
            o.z = 0.6f * n4.z + sc * c.z;
            o.w = 0.6f * n4.w + sc * c.w;
            ob[j] = o;
        }
    }
}

// ---------------- windowed weighted blend into output ----------------
__global__ void __launch_bounds__(256) k_out(float* __restrict__ out) {
    int pos = blockIdx.x;
    int b = pos >> 11;
    int p = pos & (SS - 1);
    int base = b * SDIFF;
    float c[WW];
    float wsum = 0.f;
    #pragma unroll
    for (int k = 0; k < WW; k++) {
        int idx = p - WW + k;
        float ck = 0.f;
        if (p >= 1 && idx >= 0) {
            int w = (p < WW) ? p : WW;
            int j = k - (WW - w);
            float lin = (w > 1) ? (0.1f + 0.9f * (float)j / (float)(w - 1)) : 0.1f;
            ck = lin * d_mw[base + idx];
        }
        c[k] = ck;
        wsum += ck;
    }
    float inv = 1.0f / fmaxf(wsum, 1e-8f);
    int d4 = threadIdx.x;
    float4 o = make_float4(0.f, 0.f, 0.f, 0.f);
    #pragma unroll
    for (int k = 0; k < WW; k++) {
        int idx = p - WW + k;
        if (c[k] != 0.f) {
            float4 v = *(const float4*)(d_blended + (size_t)(base + idx) * DD + d4 * 4);
            o.x = fmaf(c[k], v.x, o.x);
            o.y = fmaf(c[k], v.y, o.y);
            o.z = fmaf(c[k], v.z, o.z);
            o.w = fmaf(c[k], v.w, o.w);
        }
    }
    o.x *= inv; o.y *= inv; o.z *= inv; o.w *= inv;
    ((float4*)out)[(size_t)pos * (DD/4) + d4] = o;
}

extern "C" void kernel_launch(void* const* d_in, const int* in_sizes, int n_in,
                              void* d_out, int out_size) {
    (void)in_sizes; (void)n_in; (void)out_size;
    const float* emb  = (const float*)d_in[0];
    const float* guid = (const float*)d_in[1];
    float* out = (float*)d_out;

    cudaFuncSetAttribute(k_mm1, cudaFuncAttributeMaxDynamicSharedMemorySize, SMEM_MM);
    cudaFuncSetAttribute(k_mm2, cudaFuncAttributeMaxDynamicSharedMemorySize, SMEM_MM);

    k_ginv<<<GG, 256>>>(guid);
    k_gbf<<<GG, 256>>>(guid);
    k_prep<<<MPAD/8, 256>>>(emb);
    k_mm1<<<dim3(64, 4), 256, SMEM_MM>>>();
    k_mm2<<<dim3(64, 8), 256, SMEM_MM>>>(guid);
    k_out<<<BB * SS, 256>>>(out);
}

// round 7
// speedup vs baseline: 2.1132x; 1.1293x over previous
#include <cuda_runtime.h>
#include <cuda_bf16.h>
#include <mma.h>
#include <cstdint>
#include <math.h>

using namespace nvcuda;

#define BB 4
#define SS 2048
#define DD 1024
#define GG 512
#define WW 8
#define SDIFF 2047
#define ND (BB*SDIFF)            // 8188
#define MPAD 8192

// mm1: bf16, CTA 128m x 256n, K-chunk 64. smem strides in elems.
#define LDA1 72                  // bf16: 144B rows
#define BUF1 55296               // (128 + 256) * 144
#define LDC1 260
#define SMEM1 135200             // 128*260*4 (epilogue) > 2*BUF1=110592 -> 133120; round up
// mm2: tf32, CTA 128m x 256n, K-chunk 32.
#define LDA2 36                  // f32: 144B rows
#define LDB2 260                 // f32: 1040B rows
#define BUF2 51712               // 128*144 + 32*1040
#define SMEM2 135200

#define CP_ASYNC16(dst, src) \
    asm volatile("cp.async.cg.shared.global [%0], [%1], 16;" :: "r"(dst), "l"(src))
#define CP_COMMIT() asm volatile("cp.async.commit_group;" ::: "memory")
#define CP_WAIT_ALL() asm volatile("cp.async.wait_group 0;" ::: "memory")

__device__ __forceinline__ uint32_t smem_u32(const void* p) {
    uint32_t a;
    asm("{ .reg .u64 t; cvta.to.shared.u64 t, %1; cvt.u32.u64 %0, t; }" : "=r"(a) : "l"(p));
    return a;
}

// ---------------- global scratch ----------------
__device__ __nv_bfloat16  d_gbf[GG * DD];             // guid/||g|| bf16 [g][k]
__device__ __nv_bfloat16  d_nbf[MPAD * DD];           // normed bf16 [r][k]
__device__ float          d_normf[(size_t)MPAD * DD]; // normed f32
__device__ float          d_mw[MPAD];                 // tanh(2*mag)
__device__ float          d_wexp[(size_t)MPAD * GG];  // exp(2*sims) f32 [r][g]
__device__ float          d_sums[MPAD];               // row sums of exp
__device__ float          d_blended[(size_t)MPAD * DD];

// ---------------- guidance: norm + bf16 normalized copy ----------------
__global__ void k_gprep(const float* __restrict__ guid) {
    int g = blockIdx.x, tid = threadIdx.x;
    const float4* row = (const float4*)(guid + (size_t)g * DD);
    float4 x = row[tid];
    float s = x.x*x.x + x.y*x.y + x.z*x.z + x.w*x.w;
    #pragma unroll
    for (int o = 16; o; o >>= 1) s += __shfl_xor_sync(0xffffffffu, s, o);
    __shared__ float red[8];
    __shared__ float sinv;
    if ((tid & 31) == 0) red[tid >> 5] = s;
    __syncthreads();
    if (tid == 0) {
        float t = 0.f;
        #pragma unroll
        for (int i = 0; i < 8; i++) t += red[i];
        sinv = 1.0f / fmaxf(sqrtf(t), 1e-8f);
    }
    __syncthreads();
    float inv = sinv;
    __nv_bfloat162* o1 = (__nv_bfloat162*)(d_gbf + (size_t)g * DD);
    __nv_bfloat162 h0, h1;
    h0.x = __float2bfloat16(x.x * inv); h0.y = __float2bfloat16(x.y * inv);
    h1.x = __float2bfloat16(x.z * inv); h1.y = __float2bfloat16(x.w * inv);
    o1[2*tid] = h0; o1[2*tid+1] = h1;
}

// ---------------- diffs -> normed (bf16 + f32), mags, zero sums ----------------
__global__ void __launch_bounds__(256) k_prep(const float* __restrict__ emb) {
    int lane = threadIdx.x & 31, wid = threadIdx.x >> 5;
    int r = blockIdx.x * 8 + wid;
    if (lane == 0) d_sums[r] = 0.f;
    __nv_bfloat162* nb = (__nv_bfloat162*)(d_nbf + (size_t)r * DD);
    float4* nf = (float4*)(d_normf + (size_t)r * DD);
    if (r >= ND) {
        __nv_bfloat162 z; z.x = __float2bfloat16(0.f); z.y = z.x;
        #pragma unroll
        for (int it = 0; it < 8; it++) {
            int v = lane + 32 * it;
            nb[2*v] = z; nb[2*v+1] = z;
            nf[v] = make_float4(0.f, 0.f, 0.f, 0.f);
        }
        return;
    }
    int b = r / SDIFF;
    int i = r - b * SDIFF;
    const float4* e0 = (const float4*)(emb + ((size_t)b * SS + i) * DD);
    float4 df[8];
    float ssq = 0.f;
    #pragma unroll
    for (int it = 0; it < 8; it++) {
        int v = lane + 32 * it;
        float4 a = e0[v + DD/4];
        float4 c = e0[v];
        df[it].x = a.x - c.x; df[it].y = a.y - c.y;
        df[it].z = a.z - c.z; df[it].w = a.w - c.w;
        ssq += df[it].x*df[it].x + df[it].y*df[it].y + df[it].z*df[it].z + df[it].w*df[it].w;
    }
    #pragma unroll
    for (int o = 16; o; o >>= 1) ssq += __shfl_xor_sync(0xffffffffu, ssq, o);
    float mag = sqrtf(ssq);
    float scale = (mag > 1e-6f) ? (1.0f / mag) : 0.0f;
    if (lane == 0) d_mw[r] = tanhf(2.0f * mag);
    #pragma unroll
    for (int it = 0; it < 8; it++) {
        int v = lane + 32 * it;
        float4 o4;
        o4.x = df[it].x * scale; o4.y = df[it].y * scale;
        o4.z = df[it].z * scale; o4.w = df[it].w * scale;
        nf[v] = o4;
        __nv_bfloat162 p0, p1;
        p0.x = __float2bfloat16(o4.x); p0.y = __float2bfloat16(o4.y);
        p1.x = __float2bfloat16(o4.z); p1.y = __float2bfloat16(o4.w);
        nb[2*v] = p0; nb[2*v+1] = p1;
    }
}

// ---------------- mm1: sims = normed x gbf^T (bf16) + exp epilogue ----------------
// grid (64, 2), 512 thr. CTA 128m x 256n, K=1024 in 16 chunks of 64. Double-buffered cp.async.
__global__ void __launch_bounds__(512, 1) k_mm1() {
    extern __shared__ __align__(128) char smem[];
    uint32_t sbase = smem_u32(smem);
    int tid = threadIdx.x, wid = tid >> 5;
    int wm = wid >> 2, wn = wid & 3;
    int m0 = blockIdx.x * 128, n0 = blockIdx.y * 256;

    wmma::fragment<wmma::accumulator, 16, 16, 16, float> acc[2][4];
    #pragma unroll
    for (int mi = 0; mi < 2; mi++)
        #pragma unroll
        for (int ni = 0; ni < 4; ni++)
            wmma::fill_fragment(acc[mi][ni], 0.0f);

    // chunk loader: A 128x64 bf16 (1024 x 16B), B 256x64 bf16 (2048 x 16B)
    auto load_chunk = [&](int kc, int buf) {
        uint32_t ab = sbase + buf * BUF1;
        #pragma unroll
        for (int i = 0; i < 2; i++) {
            int q = tid + i * 512;
            int r = q >> 3, v = q & 7;
            const char* src = (const char*)d_nbf + ((size_t)(m0 + r) * DD + kc * 64 + v * 8) * 2;
            CP_ASYNC16(ab + r * 144 + v * 16, src);
        }
        uint32_t bb = ab + 18432;
        #pragma unroll
        for (int i = 0; i < 4; i++) {
            int q = tid + i * 512;
            int r = q >> 3, v = q & 7;
            const char* src = (const char*)d_gbf + ((size_t)(n0 + r) * DD + kc * 64 + v * 8) * 2;
            CP_ASYNC16(bb + r * 144 + v * 16, src);
        }
        CP_COMMIT();
    };

    load_chunk(0, 0);
    for (int kc = 0; kc < 16; kc++) {
        CP_WAIT_ALL();
        __syncthreads();
        if (kc < 15) load_chunk(kc + 1, (kc + 1) & 1);
        const __nv_bfloat16* As = (const __nv_bfloat16*)(smem + (kc & 1) * BUF1);
        const __nv_bfloat16* Bs = As + 9216;   // 18432 B
        #pragma unroll
        for (int ks = 0; ks < 4; ks++) {
            wmma::fragment<wmma::matrix_a, 16, 16, 16, __nv_bfloat16, wmma::row_major> af[2];
            wmma::fragment<wmma::matrix_b, 16, 16, 16, __nv_bfloat16, wmma::col_major> bf[4];
            #pragma unroll
            for (int mi = 0; mi < 2; mi++)
                wmma::load_matrix_sync(af[mi], As + (wm*32 + mi*16) * LDA1 + ks*16, LDA1);
            #pragma unroll
            for (int ni = 0; ni < 4; ni++)
                wmma::load_matrix_sync(bf[ni], Bs + (wn*64 + ni*16) * LDA1 + ks*16, LDA1);
            #pragma unroll
            for (int mi = 0; mi < 2; mi++)
                #pragma unroll
                for (int ni = 0; ni < 4; ni++)
                    wmma::mma_sync(acc[mi][ni], af[mi], bf[ni], acc[mi][ni]);
        }
    }
    __syncthreads();
    float* Cs = (float*)smem;   // [128][LDC1]
    #pragma unroll
    for (int mi = 0; mi < 2; mi++)
        #pragma unroll
        for (int ni = 0; ni < 4; ni++)
            wmma::store_matrix_sync(Cs + (wm*32 + mi*16) * LDC1 + wn*64 + ni*16,
                                    acc[mi][ni], LDC1, wmma::mem_row_major);
    __syncthreads();

    int row = tid >> 2, c0 = (tid & 3) * 64;
    float sum = 0.f;
    float* wout = d_wexp + (size_t)(m0 + row) * GG + n0 + c0;
    #pragma unroll 4
    for (int j = 0; j < 64; j += 4) {
        float4 e;
        e.x = __expf(2.0f * Cs[row * LDC1 + c0 + j + 0]);
        e.y = __expf(2.0f * Cs[row * LDC1 + c0 + j + 1]);
        e.z = __expf(2.0f * Cs[row * LDC1 + c0 + j + 2]);
        e.w = __expf(2.0f * Cs[row * LDC1 + c0 + j + 3]);
        sum += e.x + e.y + e.z + e.w;
        *(float4*)(wout + j) = e;
    }
    atomicAdd(&d_sums[m0 + row], sum);
}

// ---------------- mm2: influence = wexp x guid (tf32) + blend epilogue ----------------
// grid (64, 4), 512 thr. CTA 128m x 256d, K=512 in 16 chunks of 32. Double-buffered cp.async.
__global__ void __launch_bounds__(512, 1) k_mm2(const float* __restrict__ guid) {
    extern __shared__ __align__(128) char smem[];
    uint32_t sbase = smem_u32(smem);
    int tid = threadIdx.x, wid = tid >> 5;
    int wm = wid >> 2, wn = wid & 3;
    int m0 = blockIdx.x * 128, n0 = blockIdx.y * 256;

    wmma::fragment<wmma::accumulator, 16, 16, 8, float> acc[2][4];
    #pragma unroll
    for (int mi = 0; mi < 2; mi++)
        #pragma unroll
        for (int ni = 0; ni < 4; ni++)
            wmma::fill_fragment(acc[mi][ni], 0.0f);

    // chunk loader: A 128x32 f32 (1024 x 16B), B 32x256 f32 (2048 x 16B)
    auto load_chunk = [&](int kc, int buf) {
        uint32_t ab = sbase + buf * BUF2;
        #pragma unroll
        for (int i = 0; i < 2; i++) {
            int q = tid + i * 512;
            int r = q >> 3, v = q & 7;
            const char* src = (const char*)d_wexp + ((size_t)(m0 + r) * GG + kc * 32 + v * 4) * 4;
            CP_ASYNC16(ab + r * 144 + v * 16, src);
        }
        uint32_t bb = ab + 18432;
        #pragma unroll
        for (int i = 0; i < 4; i++) {
            int q = tid + i * 512;
            int rb = q >> 6, vb = q & 63;
            const char* src = (const char*)guid + ((size_t)(kc * 32 + rb) * DD + n0 + vb * 4) * 4;
            CP_ASYNC16(bb + rb * 1040 + vb * 16, src);
        }
        CP_COMMIT();
    };

    load_chunk(0, 0);
    for (int kc = 0; kc < 16; kc++) {
        CP_WAIT_ALL();
        __syncthreads();
        if (kc < 15) load_chunk(kc + 1, (kc + 1) & 1);
        const float* As = (const float*)(smem + (kc & 1) * BUF2);
        const float* Bs = As + 4608;   // 18432 B
        #pragma unroll
        for (int ks = 0; ks < 4; ks++) {
            wmma::fragment<wmma::matrix_a, 16, 16, 8, wmma::precision::tf32, wmma::row_major> af[2];
            wmma::fragment<wmma::matrix_b, 16, 16, 8, wmma::precision::tf32, wmma::row_major> bf[4];
            #pragma unroll
            for (int mi = 0; mi < 2; mi++) {
                wmma::load_matrix_sync(af[mi], As + (wm*32 + mi*16) * LDA2 + ks*8, LDA2);
                #pragma unroll
                for (int e = 0; e < af[mi].num_elements; e++)
                    af[mi].x[e] = wmma::__float_to_tf32(af[mi].x[e]);
            }
            #pragma unroll
            for (int ni = 0; ni < 4; ni++) {
                wmma::load_matrix_sync(bf[ni], Bs + (ks*8) * LDB2 + wn*64 + ni*16, LDB2);
                #pragma unroll
                for (int e = 0; e < bf[ni].num_elements; e++)
                    bf[ni].x[e] = wmma::__float_to_tf32(bf[ni].x[e]);
            }
            #pragma unroll
            for (int mi = 0; mi < 2; mi++)
                #pragma unroll
                for (int ni = 0; ni < 4; ni++)
                    wmma::mma_sync(acc[mi][ni], af[mi], bf[ni], acc[mi][ni]);
        }
    }
    __syncthreads();
    float* Cs = (float*)smem;   // [128][LDC1]
    #pragma unroll
    for (int mi = 0; mi < 2; mi++)
        #pragma unroll
        for (int ni = 0; ni < 4; ni++)
            wmma::store_matrix_sync(Cs + (wm*32 + mi*16) * LDC1 + wn*64 + ni*16,
                                    acc[mi][ni], LDC1, wmma::mem_row_major);
    __syncthreads();

    int row = tid >> 2, c0 = (tid & 3) * 64;
    int r = m0 + row;
    if (r < ND) {
        float sc = 0.4f / d_sums[r];
        const float4* nf = (const float4*)(d_normf + (size_t)r * DD + n0 + c0);
        float4* ob = (float4*)(d_blended + (size_t)r * DD + n0 + c0);
        #pragma unroll 4
        for (int j = 0; j < 16; j++) {
            float4 c = *(const float4*)&Cs[row * LDC1 + c0 + j * 4];
            float4 n4 = nf[j];
            float4 o;
            o.x = 0.6f * n4.x + sc * c.x;
            o.y = 0.6f * n4.y + sc * c.y;
            o.z = 0.6f * n4.z + sc * c.z;
            o.w = 0.6f * n4.w + sc * c.w;
            ob[j] = o;
        }
    }
}

// ---------------- windowed weighted blend into output ----------------
__global__ void __launch_bounds__(256) k_out(float* __restrict__ out) {
    int pos = blockIdx.x;
    int b = pos >> 11;
    int p = pos & (SS - 1);
    int base = b * SDIFF;
    float c[WW];
    float wsum = 0.f;
    #pragma unroll
    for (int k = 0; k < WW; k++) {
        int idx = p - WW + k;
        float ck = 0.f;
        if (p >= 1 && idx >= 0) {
            int w = (p < WW) ? p : WW;
            int j = k - (WW - w);
            float lin = (w > 1) ? (0.1f + 0.9f * (float)j / (float)(w - 1)) : 0.1f;
            ck = lin * d_mw[base + idx];
        }
        c[k] = ck;
        wsum += ck;
    }
    float inv = 1.0f / fmaxf(wsum, 1e-8f);
    int d4 = threadIdx.x;
    float4 o = make_float4(0.f, 0.f, 0.f, 0.f);
    #pragma unroll
    for (int k = 0; k < WW; k++) {
        int idx = p - WW + k;
        if (c[k] != 0.f) {
            float4 v = *(const float4*)(d_blended + (size_t)(base + idx) * DD + d4 * 4);
            o.x = fmaf(c[k], v.x, o.x);
            o.y = fmaf(c[k], v.y, o.y);
            o.z = fmaf(c[k], v.z, o.z);
            o.w = fmaf(c[k], v.w, o.w);
        }
    }
    o.x *= inv; o.y *= inv; o.z *= inv; o.w *= inv;
    ((float4*)out)[(size_t)pos * (DD/4) + d4] = o;
}

extern "C" void kernel_launch(void* const* d_in, const int* in_sizes, int n_in,
                              void* d_out, int out_size) {
    (void)in_sizes; (void)n_in; (void)out_size;
    const float* emb  = (const float*)d_in[0];
    const float* guid = (const float*)d_in[1];
    float* out = (float*)d_out;

    cudaFuncSetAttribute(k_mm1, cudaFuncAttributeMaxDynamicSharedMemorySize, SMEM1);
    cudaFuncSetAttribute(k_mm2, cudaFuncAttributeMaxDynamicSharedMemorySize, SMEM2);

    k_gprep<<<GG, 256>>>(guid);
    k_prep<<<MPAD/8, 256>>>(emb);
    k_mm1<<<dim3(64, 2), 512, SMEM1>>>();
    k_mm2<<<dim3(64, 4), 512, SMEM2>>>(guid);
    k_out<<<BB * SS, 256>>>(out);
}

// round 8
// speedup vs baseline: 2.1391x; 1.0123x over previous
#include <cuda_runtime.h>
#include <cuda_bf16.h>
#include <mma.h>
#include <cstdint>
#include <math.h>

using namespace nvcuda;

#define BB 4
#define SS 2048
#define DD 1024
#define GG 512
#define WW 8
#define SDIFF 2047
#define ND (BB*SDIFF)            // 8188
#define MPAD 8192

// mm1: bf16, CTA 128m x 256n, K-chunk 64, 3-stage.
#define LDA1 72                  // bf16 elems (144B rows)
#define BUF1 55296               // 128*144 + 256*144
#define LDC1 260
#define SMEM1 165888             // 3*BUF1 (> epilogue 133120)
// mm2: tf32, CTA 128m x 256n, K-chunk 32, 3-stage.
#define LDA2 36                  // f32 elems (144B rows)
#define LDB2 260                 // f32 elems (1040B rows)
#define BUF2 51712               // 128*144 + 32*1040
#define SMEM2 155136             // 3*BUF2 (> epilogue 133120)

#define CP_ASYNC16(dst, src) \
    asm volatile("cp.async.cg.shared.global [%0], [%1], 16;" :: "r"(dst), "l"(src))
#define CP_COMMIT() asm volatile("cp.async.commit_group;" ::: "memory")
#define CP_WAIT1() asm volatile("cp.async.wait_group 1;" ::: "memory")
#define CP_WAIT0() asm volatile("cp.async.wait_group 0;" ::: "memory")

__device__ __forceinline__ uint32_t smem_u32(const void* p) {
    uint32_t a;
    asm("{ .reg .u64 t; cvta.to.shared.u64 t, %1; cvt.u32.u64 %0, t; }" : "=r"(a) : "l"(p));
    return a;
}
__device__ __forceinline__ float tf32_round(float x) {
    uint32_t u;
    asm("cvt.rna.tf32.f32 %0, %1;" : "=r"(u) : "f"(x));
    return __uint_as_float(u);
}

// ---------------- global scratch ----------------
__device__ __nv_bfloat16  d_gbf[GG * DD];             // guid/||g|| bf16 [g][k]
__device__ float          d_gtf[GG * DD];             // guid tf32-rounded [g][d]
__device__ __nv_bfloat16  d_nbf[MPAD * DD];           // normed bf16 [r][k]
__device__ float          d_normf[(size_t)MPAD * DD]; // normed f32
__device__ float          d_mw[MPAD];                 // tanh(2*mag)
__device__ float          d_wexp[(size_t)MPAD * GG];  // exp(2*sims) tf32-rounded [r][g]
__device__ float          d_sums[MPAD];               // row sums of exp (unrounded)
__device__ float          d_blended[(size_t)MPAD * DD];

// ---------------- guidance: norm + bf16 normalized + tf32 copy ----------------
__global__ void k_gprep(const float* __restrict__ guid) {
    int g = blockIdx.x, tid = threadIdx.x;
    const float4* row = (const float4*)(guid + (size_t)g * DD);
    float4 x = row[tid];
    float s = x.x*x.x + x.y*x.y + x.z*x.z + x.w*x.w;
    #pragma unroll
    for (int o = 16; o; o >>= 1) s += __shfl_xor_sync(0xffffffffu, s, o);
    __shared__ float red[8];
    __shared__ float sinv;
    if ((tid & 31) == 0) red[tid >> 5] = s;
    __syncthreads();
    if (tid == 0) {
        float t = 0.f;
        #pragma unroll
        for (int i = 0; i < 8; i++) t += red[i];
        sinv = 1.0f / fmaxf(sqrtf(t), 1e-8f);
    }
    __syncthreads();
    float inv = sinv;
    __nv_bfloat162* o1 = (__nv_bfloat162*)(d_gbf + (size_t)g * DD);
    __nv_bfloat162 h0, h1;
    h0.x = __float2bfloat16(x.x * inv); h0.y = __float2bfloat16(x.y * inv);
    h1.x = __float2bfloat16(x.z * inv); h1.y = __float2bfloat16(x.w * inv);
    o1[2*tid] = h0; o1[2*tid+1] = h1;
    float4 t4;
    t4.x = tf32_round(x.x); t4.y = tf32_round(x.y);
    t4.z = tf32_round(x.z); t4.w = tf32_round(x.w);
    ((float4*)(d_gtf + (size_t)g * DD))[tid] = t4;
}

// ---------------- diffs -> normed (bf16 + f32), mags, zero sums ----------------
__global__ void __launch_bounds__(256) k_prep(const float* __restrict__ emb) {
    int lane = threadIdx.x & 31, wid = threadIdx.x >> 5;
    int r = blockIdx.x * 8 + wid;
    if (lane == 0) d_sums[r] = 0.f;
    __nv_bfloat162* nb = (__nv_bfloat162*)(d_nbf + (size_t)r * DD);
    float4* nf = (float4*)(d_normf + (size_t)r * DD);
    if (r >= ND) {
        __nv_bfloat162 z; z.x = __float2bfloat16(0.f); z.y = z.x;
        #pragma unroll
        for (int it = 0; it < 8; it++) {
            int v = lane + 32 * it;
            nb[2*v] = z; nb[2*v+1] = z;
            nf[v] = make_float4(0.f, 0.f, 0.f, 0.f);
        }
        return;
    }
    int b = r / SDIFF;
    int i = r - b * SDIFF;
    const float4* e0 = (const float4*)(emb + ((size_t)b * SS + i) * DD);
    float4 df[8];
    float ssq = 0.f;
    #pragma unroll
    for (int it = 0; it < 8; it++) {
        int v = lane + 32 * it;
        float4 a = e0[v + DD/4];
        float4 c = e0[v];
        df[it].x = a.x - c.x; df[it].y = a.y - c.y;
        df[it].z = a.z - c.z; df[it].w = a.w - c.w;
        ssq += df[it].x*df[it].x + df[it].y*df[it].y + df[it].z*df[it].z + df[it].w*df[it].w;
    }
    #pragma unroll
    for (int o = 16; o; o >>= 1) ssq += __shfl_xor_sync(0xffffffffu, ssq, o);
    float mag = sqrtf(ssq);
    float scale = (mag > 1e-6f) ? (1.0f / mag) : 0.0f;
    if (lane == 0) d_mw[r] = tanhf(2.0f * mag);
    #pragma unroll
    for (int it = 0; it < 8; it++) {
        int v = lane + 32 * it;
        float4 o4;
        o4.x = df[it].x * scale; o4.y = df[it].y * scale;
        o4.z = df[it].z * scale; o4.w = df[it].w * scale;
        nf[v] = o4;
        __nv_bfloat162 p0, p1;
        p0.x = __float2bfloat16(o4.x); p0.y = __float2bfloat16(o4.y);
        p1.x = __float2bfloat16(o4.z); p1.y = __float2bfloat16(o4.w);
        nb[2*v] = p0; nb[2*v+1] = p1;
    }
}

// ---------------- mm1: sims = normed x gbf^T (bf16) + exp epilogue ----------------
// grid (64, 2), 512 thr. CTA 128m x 256n, K=1024 in 16 chunks of 64. 3-stage cp.async.
__global__ void __launch_bounds__(512, 1) k_mm1() {
    extern __shared__ __align__(128) char smem[];
    uint32_t sbase = smem_u32(smem);
    int tid = threadIdx.x, wid = tid >> 5;
    int wm = wid >> 2, wn = wid & 3;
    int m0 = blockIdx.x * 128, n0 = blockIdx.y * 256;

    wmma::fragment<wmma::accumulator, 16, 16, 16, float> acc[2][4];
    #pragma unroll
    for (int mi = 0; mi < 2; mi++)
        #pragma unroll
        for (int ni = 0; ni < 4; ni++)
            wmma::fill_fragment(acc[mi][ni], 0.0f);

    auto load_chunk = [&](int kc, int buf) {
        uint32_t ab = sbase + buf * BUF1;
        #pragma unroll
        for (int i = 0; i < 2; i++) {
            int q = tid + i * 512;
            int r = q >> 3, v = q & 7;
            const char* src = (const char*)d_nbf + ((size_t)(m0 + r) * DD + kc * 64 + v * 8) * 2;
            CP_ASYNC16(ab + r * 144 + v * 16, src);
        }
        uint32_t bb = ab + 18432;
        #pragma unroll
        for (int i = 0; i < 4; i++) {
            int q = tid + i * 512;
            int r = q >> 3, v = q & 7;
            const char* src = (const char*)d_gbf + ((size_t)(n0 + r) * DD + kc * 64 + v * 8) * 2;
            CP_ASYNC16(bb + r * 144 + v * 16, src);
        }
        CP_COMMIT();
    };

    load_chunk(0, 0);
    load_chunk(1, 1);
    for (int kc = 0; kc < 16; kc++) {
        CP_WAIT1();
        __syncthreads();
        if (kc + 2 < 16) load_chunk(kc + 2, (kc + 2) % 3);
        const __nv_bfloat16* As = (const __nv_bfloat16*)(smem + (kc % 3) * BUF1);
        const __nv_bfloat16* Bs = As + 9216;
        #pragma unroll
        for (int ks = 0; ks < 4; ks++) {
            wmma::fragment<wmma::matrix_a, 16, 16, 16, __nv_bfloat16, wmma::row_major> af[2];
            wmma::fragment<wmma::matrix_b, 16, 16, 16, __nv_bfloat16, wmma::col_major> bf[4];
            #pragma unroll
            for (int mi = 0; mi < 2; mi++)
                wmma::load_matrix_sync(af[mi], As + (wm*32 + mi*16) * LDA1 + ks*16, LDA1);
            #pragma unroll
            for (int ni = 0; ni < 4; ni++)
                wmma::load_matrix_sync(bf[ni], Bs + (wn*64 + ni*16) * LDA1 + ks*16, LDA1);
            #pragma unroll
            for (int mi = 0; mi < 2; mi++)
                #pragma unroll
                for (int ni = 0; ni < 4; ni++)
                    wmma::mma_sync(acc[mi][ni], af[mi], bf[ni], acc[mi][ni]);
        }
    }
    CP_WAIT0();
    __syncthreads();
    float* Cs = (float*)smem;   // [128][LDC1]
    #pragma unroll
    for (int mi = 0; mi < 2; mi++)
        #pragma unroll
        for (int ni = 0; ni < 4; ni++)
            wmma::store_matrix_sync(Cs + (wm*32 + mi*16) * LDC1 + wn*64 + ni*16,
                                    acc[mi][ni], LDC1, wmma::mem_row_major);
    __syncthreads();

    int row = tid >> 2, c0 = (tid & 3) * 64;
    float sum = 0.f;
    float* wout = d_wexp + (size_t)(m0 + row) * GG + n0 + c0;
    #pragma unroll 4
    for (int j = 0; j < 64; j += 4) {
        float e0 = __expf(2.0f * Cs[row * LDC1 + c0 + j + 0]);
        float e1 = __expf(2.0f * Cs[row * LDC1 + c0 + j + 1]);
        float e2 = __expf(2.0f * Cs[row * LDC1 + c0 + j + 2]);
        float e3 = __expf(2.0f * Cs[row * LDC1 + c0 + j + 3]);
        sum += e0 + e1 + e2 + e3;
        float4 e;
        e.x = tf32_round(e0); e.y = tf32_round(e1);
        e.z = tf32_round(e2); e.w = tf32_round(e3);
        *(float4*)(wout + j) = e;
    }
    atomicAdd(&d_sums[m0 + row], sum);
}

// ---------------- mm2: influence = wexp x gtf (tf32, pre-rounded) + blend epilogue ----------------
// grid 128, 512 thr, persistent 2 tiles. CTA 128m x 256d, K=512 in 16 chunks of 32. 3-stage.
__global__ void __launch_bounds__(512, 1) k_mm2() {
    extern __shared__ __align__(128) char smem[];
    uint32_t sbase = smem_u32(smem);
    int tid = threadIdx.x, wid = tid >> 5;
    int wm = wid >> 2, wn = wid & 3;

    for (int rep = 0; rep < 2; rep++) {
        int t = blockIdx.x + rep * 128;
        int m0 = (t & 63) * 128, n0 = (t >> 6) * 256;

        wmma::fragment<wmma::accumulator, 16, 16, 8, float> acc[2][4];
        #pragma unroll
        for (int mi = 0; mi < 2; mi++)
            #pragma unroll
            for (int ni = 0; ni < 4; ni++)
                wmma::fill_fragment(acc[mi][ni], 0.0f);

        auto load_chunk = [&](int kc, int buf) {
            uint32_t ab = sbase + buf * BUF2;
            #pragma unroll
            for (int i = 0; i < 2; i++) {
                int q = tid + i * 512;
                int r = q >> 3, v = q & 7;
                const char* src = (const char*)d_wexp + ((size_t)(m0 + r) * GG + kc * 32 + v * 4) * 4;
                CP_ASYNC16(ab + r * 144 + v * 16, src);
            }
            uint32_t bb = ab + 18432;
            #pragma unroll
            for (int i = 0; i < 4; i++) {
                int q = tid + i * 512;
                int rb = q >> 6, vb = q & 63;
                const char* src = (const char*)d_gtf + ((size_t)(kc * 32 + rb) * DD + n0 + vb * 4) * 4;
                CP_ASYNC16(bb + rb * 1040 + vb * 16, src);
            }
            CP_COMMIT();
        };

        load_chunk(0, 0);
        load_chunk(1, 1);
        for (int kc = 0; kc < 16; kc++) {
            CP_WAIT1();
            __syncthreads();
            if (kc + 2 < 16) load_chunk(kc + 2, (kc + 2) % 3);
            const float* As = (const float*)(smem + (kc % 3) * BUF2);
            const float* Bs = As + 4608;
            #pragma unroll
            for (int ks = 0; ks < 4; ks++) {
                wmma::fragment<wmma::matrix_a, 16, 16, 8, wmma::precision::tf32, wmma::row_major> af[2];
                wmma::fragment<wmma::matrix_b, 16, 16, 8, wmma::precision::tf32, wmma::row_major> bf[4];
                #pragma unroll
                for (int mi = 0; mi < 2; mi++)
                    wmma::load_matrix_sync(af[mi], As + (wm*32 + mi*16) * LDA2 + ks*8, LDA2);
                #pragma unroll
                for (int ni = 0; ni < 4; ni++)
                    wmma::load_matrix_sync(bf[ni], Bs + (ks*8) * LDB2 + wn*64 + ni*16, LDB2);
                #pragma unroll
                for (int mi = 0; mi < 2; mi++)
                    #pragma unroll
                    for (int ni = 0; ni < 4; ni++)
                        wmma::mma_sync(acc[mi][ni], af[mi], bf[ni], acc[mi][ni]);
            }
        }
        CP_WAIT0();
        __syncthreads();
        float* Cs = (float*)smem;   // [128][LDC1]
        #pragma unroll
        for (int mi = 0; mi < 2; mi++)
            #pragma unroll
            for (int ni = 0; ni < 4; ni++)
                wmma::store_matrix_sync(Cs + (wm*32 + mi*16) * LDC1 + wn*64 + ni*16,
                                        acc[mi][ni], LDC1, wmma::mem_row_major);
        __syncthreads();

        int row = tid >> 2, c0 = (tid & 3) * 64;
        int r = m0 + row;
        if (r < ND) {
            float sc = 0.4f / d_sums[r];
            const float4* nf = (const float4*)(d_normf + (size_t)r * DD + n0 + c0);
            float4* ob = (float4*)(d_blended + (size_t)r * DD + n0 + c0);
            #pragma unroll 4
            for (int j = 0; j < 16; j++) {
                float4 c = *(const float4*)&Cs[row * LDC1 + c0 + j * 4];
                float4 n4 = nf[j];
                float4 o;
                o.x = 0.6f * n4.x + sc * c.x;
                o.y = 0.6f * n4.y + sc * c.y;
                o.z = 0.6f * n4.z + sc * c.z;
                o.w = 0.6f * n4.w + sc * c.w;
                ob[j] = o;
            }
        }
        __syncthreads();   // protect smem before next rep
    }
}

// ---------------- windowed weighted blend into output ----------------
__global__ void __launch_bounds__(256) k_out(float* __restrict__ out) {
    int pos = blockIdx.x;
    int b = pos >> 11;
    int p = pos & (SS - 1);
    int base = b * SDIFF;
    float c[WW];
    float wsum = 0.f;
    #pragma unroll
    for (int k = 0; k < WW; k++) {
        int idx = p - WW + k;
        float ck = 0.f;
        if (p >= 1 && idx >= 0) {
            int w = (p < WW) ? p : WW;
            int j = k - (WW - w);
            float lin = (w > 1) ? (0.1f + 0.9f * (float)j / (float)(w - 1)) : 0.1f;
            ck = lin * d_mw[base + idx];
        }
        c[k] = ck;
        wsum += ck;
    }
    float inv = 1.0f / fmaxf(wsum, 1e-8f);
    int d4 = threadIdx.x;
    float4 o = make_float4(0.f, 0.f, 0.f, 0.f);
    #pragma unroll
    for (int k = 0; k < WW; k++) {
        int idx = p - WW + k;
        if (c[k] != 0.f) {
            float4 v = *(const float4*)(d_blended + (size_t)(base + idx) * DD + d4 * 4);
            o.x = fmaf(c[k], v.x, o.x);
            o.y = fmaf(c[k], v.y, o.y);
            o.z = fmaf(c[k], v.z, o.z);
            o.w = fmaf(c[k], v.w, o.w);
        }
    }
    o.x *= inv; o.y *= inv; o.z *= inv; o.w *= inv;
    ((float4*)out)[(size_t)pos * (DD/4) + d4] = o;
}

extern "C" void kernel_launch(void* const* d_in, const int* in_sizes, int n_in,
                              void* d_out, int out_size) {
    (void)in_sizes; (void)n_in; (void)out_size;
    const float* emb  = (const float*)d_in[0];
    const float* guid = (const float*)d_in[1];
    float* out = (float*)d_out;

    cudaFuncSetAttribute(k_mm1, cudaFuncAttributeMaxDynamicSharedMemorySize, SMEM1);
    cudaFuncSetAttribute(k_mm2, cudaFuncAttributeMaxDynamicSharedMemorySize, SMEM2);

    k_gprep<<<GG, 256>>>(guid);
    k_prep<<<MPAD/8, 256>>>(emb);
    k_mm1<<<dim3(64, 2), 512, SMEM1>>>();
    k_mm2<<<128, 512, SMEM2>>>();
    k_out<<<BB * SS, 256>>>(out);
}

// round 9
// speedup vs baseline: 2.2273x; 1.0412x over previous
#include <cuda_runtime.h>
#include <cuda_bf16.h>
#include <mma.h>
#include <cstdint>
#include <math.h>

using namespace nvcuda;

#define BB 4
#define SS 2048
#define DD 1024
#define GG 512
#define WW 8
#define SDIFF 2047
#define ND (BB*SDIFF)            // 8188
#define MPAD 8192

// mm1: bf16, CTA 128m x 128n, 256 thr, K-chunk 64, 3-stage, 2 CTA/SM.
#define LDA1 72                  // bf16 elems (144B rows)
#define BUF1 36864               // (128+128)*144
#define SMEM1 110592             // 3*BUF1
// mm2: tf32, CTA 128m x 128n, 256 thr, K-chunk 32, 3-stage, 2 CTA/SM.
#define LDA2 36                  // f32 elems (144B rows)
#define LDB2 132                 // f32 elems (528B rows)
#define BUF2 35328               // 128*144 + 32*528
#define SMEM2 105984             // 3*BUF2
#define LDC1 132                 // epilogue f32 stride (128*132*4 = 67584 fits both)

#define CP_ASYNC16(dst, src) \
    asm volatile("cp.async.cg.shared.global [%0], [%1], 16;" :: "r"(dst), "l"(src))
#define CP_COMMIT() asm volatile("cp.async.commit_group;" ::: "memory")
#define CP_WAIT1() asm volatile("cp.async.wait_group 1;" ::: "memory")
#define CP_WAIT0() asm volatile("cp.async.wait_group 0;" ::: "memory")

__device__ __forceinline__ uint32_t smem_u32(const void* p) {
    uint32_t a;
    asm("{ .reg .u64 t; cvta.to.shared.u64 t, %1; cvt.u32.u64 %0, t; }" : "=r"(a) : "l"(p));
    return a;
}
__device__ __forceinline__ float tf32_round(float x) {
    uint32_t u;
    asm("cvt.rna.tf32.f32 %0, %1;" : "=r"(u) : "f"(x));
    return __uint_as_float(u);
}

// ---------------- global scratch ----------------
__device__ __nv_bfloat16  d_gbf[GG * DD];             // guid/||g|| bf16 [g][k]
__device__ float          d_gtf[GG * DD];             // guid tf32-rounded [g][d]
__device__ __nv_bfloat16  d_nbf[MPAD * DD];           // normed bf16 [r][k]
__device__ float          d_normf[(size_t)MPAD * DD]; // normed f32
__device__ float          d_mw[MPAD];                 // tanh(2*mag)
__device__ float          d_wexp[(size_t)MPAD * GG];  // exp(2*sims) tf32-rounded [r][g]
__device__ float          d_sums[MPAD];               // row sums of exp (unrounded)
__device__ float          d_blended[(size_t)MPAD * DD];

// ---------------- guidance: norm + bf16 normalized + tf32 copy ----------------
__global__ void k_gprep(const float* __restrict__ guid) {
    int g = blockIdx.x, tid = threadIdx.x;
    const float4* row = (const float4*)(guid + (size_t)g * DD);
    float4 x = row[tid];
    float s = x.x*x.x + x.y*x.y + x.z*x.z + x.w*x.w;
    #pragma unroll
    for (int o = 16; o; o >>= 1) s += __shfl_xor_sync(0xffffffffu, s, o);
    __shared__ float red[8];
    __shared__ float sinv;
    if ((tid & 31) == 0) red[tid >> 5] = s;
    __syncthreads();
    if (tid == 0) {
        float t = 0.f;
        #pragma unroll
        for (int i = 0; i < 8; i++) t += red[i];
        sinv = 1.0f / fmaxf(sqrtf(t), 1e-8f);
    }
    __syncthreads();
    float inv = sinv;
    __nv_bfloat162* o1 = (__nv_bfloat162*)(d_gbf + (size_t)g * DD);
    __nv_bfloat162 h0, h1;
    h0.x = __float2bfloat16(x.x * inv); h0.y = __float2bfloat16(x.y * inv);
    h1.x = __float2bfloat16(x.z * inv); h1.y = __float2bfloat16(x.w * inv);
    o1[2*tid] = h0; o1[2*tid+1] = h1;
    float4 t4;
    t4.x = tf32_round(x.x); t4.y = tf32_round(x.y);
    t4.z = tf32_round(x.z); t4.w = tf32_round(x.w);
    ((float4*)(d_gtf + (size_t)g * DD))[tid] = t4;
}

// ---------------- diffs -> normed (bf16 + f32), mags, zero sums ----------------
__global__ void __launch_bounds__(256) k_prep(const float* __restrict__ emb) {
    int lane = threadIdx.x & 31, wid = threadIdx.x >> 5;
    int r = blockIdx.x * 8 + wid;
    if (lane == 0) d_sums[r] = 0.f;
    __nv_bfloat162* nb = (__nv_bfloat162*)(d_nbf + (size_t)r * DD);
    float4* nf = (float4*)(d_normf + (size_t)r * DD);
    if (r >= ND) {
        __nv_bfloat162 z; z.x = __float2bfloat16(0.f); z.y = z.x;
        #pragma unroll
        for (int it = 0; it < 8; it++) {
            int v = lane + 32 * it;
            nb[2*v] = z; nb[2*v+1] = z;
            nf[v] = make_float4(0.f, 0.f, 0.f, 0.f);
        }
        return;
    }
    int b = r / SDIFF;
    int i = r - b * SDIFF;
    const float4* e0 = (const float4*)(emb + ((size_t)b * SS + i) * DD);
    float4 df[8];
    float ssq = 0.f;
    #pragma unroll
    for (int it = 0; it < 8; it++) {
        int v = lane + 32 * it;
        float4 a = e0[v + DD/4];
        float4 c = e0[v];
        df[it].x = a.x - c.x; df[it].y = a.y - c.y;
        df[it].z = a.z - c.z; df[it].w = a.w - c.w;
        ssq += df[it].x*df[it].x + df[it].y*df[it].y + df[it].z*df[it].z + df[it].w*df[it].w;
    }
    #pragma unroll
    for (int o = 16; o; o >>= 1) ssq += __shfl_xor_sync(0xffffffffu, ssq, o);
    float mag = sqrtf(ssq);
    float scale = (mag > 1e-6f) ? (1.0f / mag) : 0.0f;
    if (lane == 0) d_mw[r] = tanhf(2.0f * mag);
    #pragma unroll
    for (int it = 0; it < 8; it++) {
        int v = lane + 32 * it;
        float4 o4;
        o4.x = df[it].x * scale; o4.y = df[it].y * scale;
        o4.z = df[it].z * scale; o4.w = df[it].w * scale;
        nf[v] = o4;
        __nv_bfloat162 p0, p1;
        p0.x = __float2bfloat16(o4.x); p0.y = __float2bfloat16(o4.y);
        p1.x = __float2bfloat16(o4.z); p1.y = __float2bfloat16(o4.w);
        nb[2*v] = p0; nb[2*v+1] = p1;
    }
}

// ---------------- mm1: sims = normed x gbf^T (bf16) + exp epilogue ----------------
// grid (64, 4), 256 thr, 2 CTA/SM. CTA 128m x 128n, K=1024 in 16 chunks of 64. 3-stage.
__global__ void __launch_bounds__(256, 2) k_mm1() {
    extern __shared__ __align__(128) char smem[];
    uint32_t sbase = smem_u32(smem);
    int tid = threadIdx.x, wid = tid >> 5;
    int wm = wid >> 1, wn = wid & 1;
    int m0 = blockIdx.x * 128, n0 = blockIdx.y * 128;

    wmma::fragment<wmma::accumulator, 16, 16, 16, float> acc[2][4];
    #pragma unroll
    for (int mi = 0; mi < 2; mi++)
        #pragma unroll
        for (int ni = 0; ni < 4; ni++)
            wmma::fill_fragment(acc[mi][ni], 0.0f);

    auto load_chunk = [&](int kc, int buf) {
        uint32_t ab = sbase + buf * BUF1;
        #pragma unroll
        for (int i = 0; i < 4; i++) {
            int q = tid + i * 256;
            int r = q >> 3, v = q & 7;
            const char* src = (const char*)d_nbf + ((size_t)(m0 + r) * DD + kc * 64 + v * 8) * 2;
            CP_ASYNC16(ab + r * 144 + v * 16, src);
        }
        uint32_t bb = ab + 18432;
        #pragma unroll
        for (int i = 0; i < 4; i++) {
            int q = tid + i * 256;
            int r = q >> 3, v = q & 7;
            const char* src = (const char*)d_gbf + ((size_t)(n0 + r) * DD + kc * 64 + v * 8) * 2;
            CP_ASYNC16(bb + r * 144 + v * 16, src);
        }
        CP_COMMIT();
    };

    load_chunk(0, 0);
    load_chunk(1, 1);
    for (int kc = 0; kc < 16; kc++) {
        CP_WAIT1();
        __syncthreads();
        if (kc + 2 < 16) load_chunk(kc + 2, (kc + 2) % 3);
        const __nv_bfloat16* As = (const __nv_bfloat16*)(smem + (kc % 3) * BUF1);
        const __nv_bfloat16* Bs = As + 9216;
        #pragma unroll
        for (int ks = 0; ks < 4; ks++) {
            wmma::fragment<wmma::matrix_a, 16, 16, 16, __nv_bfloat16, wmma::row_major> af[2];
            wmma::fragment<wmma::matrix_b, 16, 16, 16, __nv_bfloat16, wmma::col_major> bf[4];
            #pragma unroll
            for (int mi = 0; mi < 2; mi++)
                wmma::load_matrix_sync(af[mi], As + (wm*32 + mi*16) * LDA1 + ks*16, LDA1);
            #pragma unroll
            for (int ni = 0; ni < 4; ni++)
                wmma::load_matrix_sync(bf[ni], Bs + (wn*64 + ni*16) * LDA1 + ks*16, LDA1);
            #pragma unroll
            for (int mi = 0; mi < 2; mi++)
                #pragma unroll
                for (int ni = 0; ni < 4; ni++)
                    wmma::mma_sync(acc[mi][ni], af[mi], bf[ni], acc[mi][ni]);
        }
    }
    CP_WAIT0();
    __syncthreads();
    float* Cs = (float*)smem;   // [128][LDC1]
    #pragma unroll
    for (int mi = 0; mi < 2; mi++)
        #pragma unroll
        for (int ni = 0; ni < 4; ni++)
            wmma::store_matrix_sync(Cs + (wm*32 + mi*16) * LDC1 + wn*64 + ni*16,
                                    acc[mi][ni], LDC1, wmma::mem_row_major);
    __syncthreads();

    int row = tid >> 1, c0 = (tid & 1) * 64;
    float sum = 0.f;
    float* wout = d_wexp + (size_t)(m0 + row) * GG + n0 + c0;
    #pragma unroll 4
    for (int j = 0; j < 64; j += 4) {
        float e0 = __expf(2.0f * Cs[row * LDC1 + c0 + j + 0]);
        float e1 = __expf(2.0f * Cs[row * LDC1 + c0 + j + 1]);
        float e2 = __expf(2.0f * Cs[row * LDC1 + c0 + j + 2]);
        float e3 = __expf(2.0f * Cs[row * LDC1 + c0 + j + 3]);
        sum += e0 + e1 + e2 + e3;
        float4 e;
        e.x = tf32_round(e0); e.y = tf32_round(e1);
        e.z = tf32_round(e2); e.w = tf32_round(e3);
        *(float4*)(wout + j) = e;
    }
    atomicAdd(&d_sums[m0 + row], sum);
}

// ---------------- mm2: influence = wexp x gtf (tf32) + blend epilogue ----------------
// grid 256, 256 thr, 2 CTA/SM, persistent 2 tiles. CTA 128m x 128n, K=512 in 16 chunks of 32.
__global__ void __launch_bounds__(256, 2) k_mm2() {
    extern __shared__ __align__(128) char smem[];
    uint32_t sbase = smem_u32(smem);
    int tid = threadIdx.x, wid = tid >> 5;
    int wm = wid >> 1, wn = wid & 1;

    for (int rep = 0; rep < 2; rep++) {
        int t = blockIdx.x + rep * 256;
        int m0 = (t & 63) * 128, n0 = (t >> 6) * 128;

        wmma::fragment<wmma::accumulator, 16, 16, 8, float> acc[2][4];
        #pragma unroll
        for (int mi = 0; mi < 2; mi++)
            #pragma unroll
            for (int ni = 0; ni < 4; ni++)
                wmma::fill_fragment(acc[mi][ni], 0.0f);

        auto load_chunk = [&](int kc, int buf) {
            uint32_t ab = sbase + buf * BUF2;
            #pragma unroll
            for (int i = 0; i < 4; i++) {
                int q = tid + i * 256;
                int r = q >> 3, v = q & 7;
                const char* src = (const char*)d_wexp + ((size_t)(m0 + r) * GG + kc * 32 + v * 4) * 4;
                CP_ASYNC16(ab + r * 144 + v * 16, src);
            }
            uint32_t bb = ab + 18432;
            #pragma unroll
            for (int i = 0; i < 4; i++) {
                int q = tid + i * 256;
                int rb = q >> 5, vb = q & 31;
                const char* src = (const char*)d_gtf + ((size_t)(kc * 32 + rb) * DD + n0 + vb * 4) * 4;
                CP_ASYNC16(bb + rb * 528 + vb * 16, src);
            }
            CP_COMMIT();
        };

        load_chunk(0, 0);
        load_chunk(1, 1);
        for (int kc = 0; kc < 16; kc++) {
            CP_WAIT1();
            __syncthreads();
            if (kc + 2 < 16) load_chunk(kc + 2, (kc + 2) % 3);
            const float* As = (const float*)(smem + (kc % 3) * BUF2);
            const float* Bs = As + 4608;
            #pragma unroll
            for (int ks = 0; ks < 4; ks++) {
                wmma::fragment<wmma::matrix_a, 16, 16, 8, wmma::precision::tf32, wmma::row_major> af[2];
                wmma::fragment<wmma::matrix_b, 16, 16, 8, wmma::precision::tf32, wmma::row_major> bf[4];
                #pragma unroll
                for (int mi = 0; mi < 2; mi++)
                    wmma::load_matrix_sync(af[mi], As + (wm*32 + mi*16) * LDA2 + ks*8, LDA2);
                #pragma unroll
                for (int ni = 0; ni < 4; ni++)
                    wmma::load_matrix_sync(bf[ni], Bs + (ks*8) * LDB2 + wn*64 + ni*16, LDB2);
                #pragma unroll
                for (int mi = 0; mi < 2; mi++)
                    #pragma unroll
                    for (int ni = 0; ni < 4; ni++)
                        wmma::mma_sync(acc[mi][ni], af[mi], bf[ni], acc[mi][ni]);
            }
        }
        CP_WAIT0();
        __syncthreads();
        float* Cs = (float*)smem;   // [128][LDC1]
        #pragma unroll
        for (int mi = 0; mi < 2; mi++)
            #pragma unroll
            for (int ni = 0; ni < 4; ni++)
                wmma::store_matrix_sync(Cs + (wm*32 + mi*16) * LDC1 + wn*64 + ni*16,
                                        acc[mi][ni], LDC1, wmma::mem_row_major);
        __syncthreads();

        int row = tid >> 1, c0 = (tid & 1) * 64;
        int r = m0 + row;
        if (r < ND) {
            float sc = 0.4f / d_sums[r];
            const float4* nf = (const float4*)(d_normf + (size_t)r * DD + n0 + c0);
            float4* ob = (float4*)(d_blended + (size_t)r * DD + n0 + c0);
            #pragma unroll 4
            for (int j = 0; j < 16; j++) {
                float4 c = *(const float4*)&Cs[row * LDC1 + c0 + j * 4];
                float4 n4 = nf[j];
                float4 o;
                o.x = 0.6f * n4.x + sc * c.x;
                o.y = 0.6f * n4.y + sc * c.y;
                o.z = 0.6f * n4.z + sc * c.z;
                o.w = 0.6f * n4.w + sc * c.w;
                ob[j] = o;
            }
        }
        __syncthreads();   // protect smem before next rep
    }
}

// ---------------- windowed weighted blend into output ----------------
__global__ void __launch_bounds__(256) k_out(float* __restrict__ out) {
    int pos = blockIdx.x;
    int b = pos >> 11;
    int p = pos & (SS - 1);
    int base = b * SDIFF;
    float c[WW];
    float wsum = 0.f;
    #pragma unroll
    for (int k = 0; k < WW; k++) {
        int idx = p - WW + k;
        float ck = 0.f;
        if (p >= 1 && idx >= 0) {
            int w = (p < WW) ? p : WW;
            int j = k - (WW - w);
            float lin = (w > 1) ? (0.1f + 0.9f * (float)j / (float)(w - 1)) : 0.1f;
            ck = lin * d_mw[base + idx];
        }
        c[k] = ck;
        wsum += ck;
    }
    float inv = 1.0f / fmaxf(wsum, 1e-8f);
    int d4 = threadIdx.x;
    float4 o = make_float4(0.f, 0.f, 0.f, 0.f);
    #pragma unroll
    for (int k = 0; k < WW; k++) {
        int idx = p - WW + k;
        if (c[k] != 0.f) {
            float4 v = *(const float4*)(d_blended + (size_t)(base + idx) * DD + d4 * 4);
            o.x = fmaf(c[k], v.x, o.x);
            o.y = fmaf(c[k], v.y, o.y);
            o.z = fmaf(c[k], v.z, o.z);
            o.w = fmaf(c[k], v.w, o.w);
        }
    }
    o.x *= inv; o.y *= inv; o.z *= inv; o.w *= inv;
    ((float4*)out)[(size_t)pos * (DD/4) + d4] = o;
}

extern "C" void kernel_launch(void* const* d_in, const int* in_sizes, int n_in,
                              void* d_out, int out_size) {
    (void)in_sizes; (void)n_in; (void)out_size;
    const float* emb  = (const float*)d_in[0];
    const float* guid = (const float*)d_in[1];
    float* out = (float*)d_out;

    cudaFuncSetAttribute(k_mm1, cudaFuncAttributeMaxDynamicSharedMemorySize, SMEM1);
    cudaFuncSetAttribute(k_mm2, cudaFuncAttributeMaxDynamicSharedMemorySize, SMEM2);

    k_gprep<<<GG, 256>>>(guid);
    k_prep<<<MPAD/8, 256>>>(emb);
    k_mm1<<<dim3(64, 4), 256, SMEM1>>>();
    k_mm2<<<256, 256, SMEM2>>>();
    k_out<<<BB * SS, 256>>>(out);
}

// round 10
// speedup vs baseline: 3.5925x; 1.6129x over previous
#include <cuda_runtime.h>
#include <cuda_fp16.h>
#include <mma.h>
#include <cstdint>
#include <math.h>

using namespace nvcuda;

#define BB 4
#define SS 2048
#define DD 1024
#define GG 512
#define WW 8
#define SDIFF 2047
#define ND (BB*SDIFF)            // 8188
#define MPAD 8192

// both GEMMs: fp16, CTA 128m x 128n, 256 thr, K-chunk 64, 3-stage, 2 CTA/SM.
#define LDA1 72                  // fp16 elems (144B rows)
#define BUF1 36864               // (128+128)*144
#define SMEM1 110592             // 3*BUF1
#define LDC1 132                 // epilogue f32 stride (128*132*4 = 67584)

#define CP_ASYNC16(dst, src) \
    asm volatile("cp.async.cg.shared.global [%0], [%1], 16;" :: "r"(dst), "l"(src))
#define CP_COMMIT() asm volatile("cp.async.commit_group;" ::: "memory")
#define CP_WAIT1() asm volatile("cp.async.wait_group 1;" ::: "memory")
#define CP_WAIT0() asm volatile("cp.async.wait_group 0;" ::: "memory")

__device__ __forceinline__ uint32_t smem_u32(const void* p) {
    uint32_t a;
    asm("{ .reg .u64 t; cvta.to.shared.u64 t, %1; cvt.u32.u64 %0, t; }" : "=r"(a) : "l"(p));
    return a;
}

// ---------------- global scratch ----------------
__device__ __half  d_gh[GG * DD];              // guid/||g|| fp16 [g][k]
__device__ __half  d_gth[DD * GG];             // guid^T fp16 [d][g]
__device__ __half  d_nh[(size_t)MPAD * DD];    // normed fp16 [r][k]
__device__ float   d_normf[(size_t)MPAD * DD]; // normed f32
__device__ float   d_mw[MPAD];                 // tanh(2*mag)
__device__ __half  d_wh[(size_t)MPAD * GG];    // exp(2*sims) fp16 [r][g]
__device__ float   d_sums[MPAD];               // row sums of exp (f32)
__device__ float   d_blended[(size_t)MPAD * DD];

// ---------------- guidance: norm + fp16 normalized [g][k] ----------------
__global__ void k_gprep(const float* __restrict__ guid) {
    int g = blockIdx.x, tid = threadIdx.x;
    const float4* row = (const float4*)(guid + (size_t)g * DD);
    float4 x = row[tid];
    float s = x.x*x.x + x.y*x.y + x.z*x.z + x.w*x.w;
    #pragma unroll
    for (int o = 16; o; o >>= 1) s += __shfl_xor_sync(0xffffffffu, s, o);
    __shared__ float red[8];
    __shared__ float sinv;
    if ((tid & 31) == 0) red[tid >> 5] = s;
    __syncthreads();
    if (tid == 0) {
        float t = 0.f;
        #pragma unroll
        for (int i = 0; i < 8; i++) t += red[i];
        sinv = 1.0f / fmaxf(sqrtf(t), 1e-8f);
    }
    __syncthreads();
    float inv = sinv;
    __half2* o1 = (__half2*)(d_gh + (size_t)g * DD);
    o1[2*tid]   = __floats2half2_rn(x.x * inv, x.y * inv);
    o1[2*tid+1] = __floats2half2_rn(x.z * inv, x.w * inv);
}

// ---------------- transpose guid -> fp16 [d][g] ----------------
__global__ void k_gt(const float* __restrict__ guid) {
    __shared__ float tile[32][33];
    int d0 = blockIdx.x * 32, g0 = blockIdx.y * 32;
    int tx = threadIdx.x, ty = threadIdx.y;
    #pragma unroll
    for (int yy = ty; yy < 32; yy += 8)
        tile[yy][tx] = guid[(size_t)(g0 + yy) * DD + (d0 + tx)];
    __syncthreads();
    #pragma unroll
    for (int yy = ty; yy < 32; yy += 8)
        d_gth[(size_t)(d0 + yy) * GG + (g0 + tx)] = __float2half_rn(tile[tx][yy]);
}

// ---------------- diffs -> normed (fp16 + f32), mags, zero sums ----------------
__global__ void __launch_bounds__(256) k_prep(const float* __restrict__ emb) {
    int lane = threadIdx.x & 31, wid = threadIdx.x >> 5;
    int r = blockIdx.x * 8 + wid;
    if (lane == 0) d_sums[r] = 0.f;
    __half2* nb = (__half2*)(d_nh + (size_t)r * DD);
    float4* nf = (float4*)(d_normf + (size_t)r * DD);
    if (r >= ND) {
        __half2 z = __floats2half2_rn(0.f, 0.f);
        #pragma unroll
        for (int it = 0; it < 8; it++) {
            int v = lane + 32 * it;
            nb[2*v] = z; nb[2*v+1] = z;
            nf[v] = make_float4(0.f, 0.f, 0.f, 0.f);
        }
        return;
    }
    int b = r / SDIFF;
    int i = r - b * SDIFF;
    const float4* e0 = (const float4*)(emb + ((size_t)b * SS + i) * DD);
    float4 df[8];
    float ssq = 0.f;
    #pragma unroll
    for (int it = 0; it < 8; it++) {
        int v = lane + 32 * it;
        float4 a = e0[v + DD/4];
        float4 c = e0[v];
        df[it].x = a.x - c.x; df[it].y = a.y - c.y;
        df[it].z = a.z - c.z; df[it].w = a.w - c.w;
        ssq += df[it].x*df[it].x + df[it].y*df[it].y + df[it].z*df[it].z + df[it].w*df[it].w;
    }
    #pragma unroll
    for (int o = 16; o; o >>= 1) ssq += __shfl_xor_sync(0xffffffffu, ssq, o);
    float mag = sqrtf(ssq);
    float scale = (mag > 1e-6f) ? (1.0f / mag) : 0.0f;
    if (lane == 0) d_mw[r] = tanhf(2.0f * mag);
    #pragma unroll
    for (int it = 0; it < 8; it++) {
        int v = lane + 32 * it;
        float4 o4;
        o4.x = df[it].x * scale; o4.y = df[it].y * scale;
        o4.z = df[it].z * scale; o4.w = df[it].w * scale;
        nf[v] = o4;
        nb[2*v]   = __floats2half2_rn(o4.x, o4.y);
        nb[2*v+1] = __floats2half2_rn(o4.z, o4.w);
    }
}

// ---------------- mm1: sims = normed x gh^T (fp16) + exp epilogue ----------------
// grid (64, 4), 256 thr, 2 CTA/SM. CTA 128m x 128n, K=1024 in 16 chunks of 64. 3-stage.
__global__ void __launch_bounds__(256, 2) k_mm1() {
    extern __shared__ __align__(128) char smem[];
    uint32_t sbase = smem_u32(smem);
    int tid = threadIdx.x, wid = tid >> 5;
    int wm = wid >> 1, wn = wid & 1;
    int m0 = blockIdx.x * 128, n0 = blockIdx.y * 128;

    wmma::fragment<wmma::accumulator, 16, 16, 16, float> acc[2][4];
    #pragma unroll
    for (int mi = 0; mi < 2; mi++)
        #pragma unroll
        for (int ni = 0; ni < 4; ni++)
            wmma::fill_fragment(acc[mi][ni], 0.0f);

    auto load_chunk = [&](int kc, int buf) {
        uint32_t ab = sbase + buf * BUF1;
        #pragma unroll
        for (int i = 0; i < 4; i++) {
            int q = tid + i * 256;
            int r = q >> 3, v = q & 7;
            const char* src = (const char*)d_nh + ((size_t)(m0 + r) * DD + kc * 64 + v * 8) * 2;
            CP_ASYNC16(ab + r * 144 + v * 16, src);
        }
        uint32_t bb = ab + 18432;
        #pragma unroll
        for (int i = 0; i < 4; i++) {
            int q = tid + i * 256;
            int r = q >> 3, v = q & 7;
            const char* src = (const char*)d_gh + ((size_t)(n0 + r) * DD + kc * 64 + v * 8) * 2;
            CP_ASYNC16(bb + r * 144 + v * 16, src);
        }
        CP_COMMIT();
    };

    load_chunk(0, 0);
    load_chunk(1, 1);
    for (int kc = 0; kc < 16; kc++) {
        CP_WAIT1();
        __syncthreads();
        if (kc + 2 < 16) load_chunk(kc + 2, (kc + 2) % 3);
        const __half* As = (const __half*)(smem + (kc % 3) * BUF1);
        const __half* Bs = As + 9216;
        #pragma unroll
        for (int ks = 0; ks < 4; ks++) {
            wmma::fragment<wmma::matrix_a, 16, 16, 16, __half, wmma::row_major> af[2];
            wmma::fragment<wmma::matrix_b, 16, 16, 16, __half, wmma::col_major> bf[4];
            #pragma unroll
            for (int mi = 0; mi < 2; mi++)
                wmma::load_matrix_sync(af[mi], As + (wm*32 + mi*16) * LDA1 + ks*16, LDA1);
            #pragma unroll
            for (int ni = 0; ni < 4; ni++)
                wmma::load_matrix_sync(bf[ni], Bs + (wn*64 + ni*16) * LDA1 + ks*16, LDA1);
            #pragma unroll
            for (int mi = 0; mi < 2; mi++)
                #pragma unroll
                for (int ni = 0; ni < 4; ni++)
                    wmma::mma_sync(acc[mi][ni], af[mi], bf[ni], acc[mi][ni]);
        }
    }
    CP_WAIT0();
    __syncthreads();
    float* Cs = (float*)smem;   // [128][LDC1]
    #pragma unroll
    for (int mi = 0; mi < 2; mi++)
        #pragma unroll
        for (int ni = 0; ni < 4; ni++)
            wmma::store_matrix_sync(Cs + (wm*32 + mi*16) * LDC1 + wn*64 + ni*16,
                                    acc[mi][ni], LDC1, wmma::mem_row_major);
    __syncthreads();

    int row = tid >> 1, c0 = (tid & 1) * 64;
    float sum = 0.f;
    __half2* wout = (__half2*)(d_wh + (size_t)(m0 + row) * GG + n0 + c0);
    #pragma unroll 4
    for (int j = 0; j < 64; j += 4) {
        float e0 = __expf(2.0f * Cs[row * LDC1 + c0 + j + 0]);
        float e1 = __expf(2.0f * Cs[row * LDC1 + c0 + j + 1]);
        float e2 = __expf(2.0f * Cs[row * LDC1 + c0 + j + 2]);
        float e3 = __expf(2.0f * Cs[row * LDC1 + c0 + j + 3]);
        sum += e0 + e1 + e2 + e3;
        wout[(j >> 1) + 0] = __floats2half2_rn(e0, e1);
        wout[(j >> 1) + 1] = __floats2half2_rn(e2, e3);
    }
    atomicAdd(&d_sums[m0 + row], sum);
}

// ---------------- mm2: influence = wh x gth^T (fp16) + blend epilogue ----------------
// grid 256, 256 thr, 2 CTA/SM, persistent 2 tiles. CTA 128m x 128d, K=512 in 8 chunks of 64.
__global__ void __launch_bounds__(256, 2) k_mm2() {
    extern __shared__ __align__(128) char smem[];
    uint32_t sbase = smem_u32(smem);
    int tid = threadIdx.x, wid = tid >> 5;
    int wm = wid >> 1, wn = wid & 1;

    for (int rep = 0; rep < 2; rep++) {
        int t = blockIdx.x + rep * 256;
        int m0 = (t & 63) * 128, n0 = (t >> 6) * 128;

        wmma::fragment<wmma::accumulator, 16, 16, 16, float> acc[2][4];
        #pragma unroll
        for (int mi = 0; mi < 2; mi++)
            #pragma unroll
            for (int ni = 0; ni < 4; ni++)
                wmma::fill_fragment(acc[mi][ni], 0.0f);

        auto load_chunk = [&](int kc, int buf) {
            uint32_t ab = sbase + buf * BUF1;
            #pragma unroll
            for (int i = 0; i < 4; i++) {
                int q = tid + i * 256;
                int r = q >> 3, v = q & 7;
                const char* src = (const char*)d_wh + ((size_t)(m0 + r) * GG + kc * 64 + v * 8) * 2;
                CP_ASYNC16(ab + r * 144 + v * 16, src);
            }
            uint32_t bb = ab + 18432;
            #pragma unroll
            for (int i = 0; i < 4; i++) {
                int q = tid + i * 256;
                int r = q >> 3, v = q & 7;
                const char* src = (const char*)d_gth + ((size_t)(n0 + r) * GG + kc * 64 + v * 8) * 2;
                CP_ASYNC16(bb + r * 144 + v * 16, src);
            }
            CP_COMMIT();
        };

        load_chunk(0, 0);
        load_chunk(1, 1);
        for (int kc = 0; kc < 8; kc++) {
            CP_WAIT1();
            __syncthreads();
            if (kc + 2 < 8) load_chunk(kc + 2, (kc + 2) % 3);
            const __half* As = (const __half*)(smem + (kc % 3) * BUF1);
            const __half* Bs = As + 9216;
            #pragma unroll
            for (int ks = 0; ks < 4; ks++) {
                wmma::fragment<wmma::matrix_a, 16, 16, 16, __half, wmma::row_major> af[2];
                wmma::fragment<wmma::matrix_b, 16, 16, 16, __half, wmma::col_major> bf[4];
                #pragma unroll
                for (int mi = 0; mi < 2; mi++)
                    wmma::load_matrix_sync(af[mi], As + (wm*32 + mi*16) * LDA1 + ks*16, LDA1);
                #pragma unroll
                for (int ni = 0; ni < 4; ni++)
                    wmma::load_matrix_sync(bf[ni], Bs + (wn*64 + ni*16) * LDA1 + ks*16, LDA1);
                #pragma unroll
                for (int mi = 0; mi < 2; mi++)
                    #pragma unroll
                    for (int ni = 0; ni < 4; ni++)
                        wmma::mma_sync(acc[mi][ni], af[mi], bf[ni], acc[mi][ni]);
            }
        }
        CP_WAIT0();
        __syncthreads();
        float* Cs = (float*)smem;   // [128][LDC1]
        #pragma unroll
        for (int mi = 0; mi < 2; mi++)
            #pragma unroll
            for (int ni = 0; ni < 4; ni++)
                wmma::store_matrix_sync(Cs + (wm*32 + mi*16) * LDC1 + wn*64 + ni*16,
                                        acc[mi][ni], LDC1, wmma::mem_row_major);
        __syncthreads();

        int row = tid >> 1, c0 = (tid & 1) * 64;
        int r = m0 + row;
        if (r < ND) {
            float sc = 0.4f / d_sums[r];
            const float4* nf = (const float4*)(d_normf + (size_t)r * DD + n0 + c0);
            float4* ob = (float4*)(d_blended + (size_t)r * DD + n0 + c0);
            #pragma unroll 4
            for (int j = 0; j < 16; j++) {
                float4 c = *(const float4*)&Cs[row * LDC1 + c0 + j * 4];
                float4 n4 = nf[j];
                float4 o;
                o.x = 0.6f * n4.x + sc * c.x;
                o.y = 0.6f * n4.y + sc * c.y;
                o.z = 0.6f * n4.z + sc * c.z;
                o.w = 0.6f * n4.w + sc * c.w;
                ob[j] = o;
            }
        }
        __syncthreads();   // protect smem before next rep
    }
}

// ---------------- windowed weighted blend into output ----------------
__global__ void __launch_bounds__(256) k_out(float* __restrict__ out) {
    int pos = blockIdx.x;
    int b = pos >> 11;
    int p = pos & (SS - 1);
    int base = b * SDIFF;
    float c[WW];
    float wsum = 0.f;
    #pragma unroll
    for (int k = 0; k < WW; k++) {
        int idx = p - WW + k;
        float ck = 0.f;
        if (p >= 1 && idx >= 0) {
            int w = (p < WW) ? p : WW;
            int j = k - (WW - w);
            float lin = (w > 1) ? (0.1f + 0.9f * (float)j / (float)(w - 1)) : 0.1f;
            ck = lin * d_mw[base + idx];
        }
        c[k] = ck;
        wsum += ck;
    }
    float inv = 1.0f / fmaxf(wsum, 1e-8f);
    int d4 = threadIdx.x;
    float4 o = make_float4(0.f, 0.f, 0.f, 0.f);
    #pragma unroll
    for (int k = 0; k < WW; k++) {
        int idx = p - WW + k;
        if (c[k] != 0.f) {
            float4 v = *(const float4*)(d_blended + (size_t)(base + idx) * DD + d4 * 4);
            o.x = fmaf(c[k], v.x, o.x);
            o.y = fmaf(c[k], v.y, o.y);
            o.z = fmaf(c[k], v.z, o.z);
            o.w = fmaf(c[k], v.w, o.w);
        }
    }
    o.x *= inv; o.y *= inv; o.z *= inv; o.w *= inv;
    ((float4*)out)[(size_t)pos * (DD/4) + d4] = o;
}

extern "C" void kernel_launch(void* const* d_in, const int* in_sizes, int n_in,
                              void* d_out, int out_size) {
    (void)in_sizes; (void)n_in; (void)out_size;
    const float* emb  = (const float*)d_in[0];
    const float* guid = (const float*)d_in[1];
    float* out = (float*)d_out;

    cudaFuncSetAttribute(k_mm1, cudaFuncAttributeMaxDynamicSharedMemorySize, SMEM1);
    cudaFuncSetAttribute(k_mm2, cudaFuncAttributeMaxDynamicSharedMemorySize, SMEM1);

    k_gprep<<<GG, 256>>>(guid);
    k_gt<<<dim3(DD/32, GG/32), dim3(32, 8)>>>(guid);
    k_prep<<<MPAD/8, 256>>>(emb);
    k_mm1<<<dim3(64, 4), 256, SMEM1>>>();
    k_mm2<<<256, 256, SMEM1>>>();
    k_out<<<BB * SS, 256>>>(out);
}

// round 11
// speedup vs baseline: 3.6284x; 1.0100x over previous
#include <cuda_runtime.h>
#include <cuda_fp16.h>
#include <mma.h>
#include <cstdint>
#include <math.h>

using namespace nvcuda;

#define BB 4
#define SS 2048
#define DD 1024
#define GG 512
#define WW 8
#define SDIFF 2047
#define ND (BB*SDIFF)            // 8188
#define MPAD 8192

// GEMMs: fp16, CTA 128m x 256n, 512 thr, K-chunk 64, 3-stage.
#define LDA1 72                  // fp16 elems (144B rows)
#define BUF1 55296               // 128*144 + 256*144
#define LDC1 260
#define SMEM1 165888             // 3*BUF1 (> epilogue 128*260*4=133120)

#define CP_ASYNC16(dst, src) \
    asm volatile("cp.async.cg.shared.global [%0], [%1], 16;" :: "r"(dst), "l"(src))
#define CP_COMMIT() asm volatile("cp.async.commit_group;" ::: "memory")
#define CP_WAIT1() asm volatile("cp.async.wait_group 1;" ::: "memory")
#define CP_WAIT0() asm volatile("cp.async.wait_group 0;" ::: "memory")

__device__ __forceinline__ uint32_t smem_u32(const void* p) {
    uint32_t a;
    asm("{ .reg .u64 t; cvta.to.shared.u64 t, %1; cvt.u32.u64 %0, t; }" : "=r"(a) : "l"(p));
    return a;
}

// ---------------- global scratch ----------------
__device__ __half  d_gh[GG * DD];              // guid/||g|| fp16 [g][k]
__device__ __half  d_gth[DD * GG];             // guid^T fp16 [d][g]
__device__ __half  d_nh[(size_t)MPAD * DD];    // normed fp16 [r][k]
__device__ float   d_mw[MPAD];                 // tanh(2*mag)
__device__ __half  d_wh[(size_t)MPAD * GG];    // exp(2*sims) fp16 [r][g]
__device__ float   d_sums[MPAD];               // row sums of exp (f32)
__device__ float   d_blended[(size_t)MPAD * DD];

// ---------------- guidance: norm + fp16 normalized [g][k] ----------------
__global__ void k_gprep(const float* __restrict__ guid) {
    int g = blockIdx.x, tid = threadIdx.x;
    const float4* row = (const float4*)(guid + (size_t)g * DD);
    float4 x = row[tid];
    float s = x.x*x.x + x.y*x.y + x.z*x.z + x.w*x.w;
    #pragma unroll
    for (int o = 16; o; o >>= 1) s += __shfl_xor_sync(0xffffffffu, s, o);
    __shared__ float red[8];
    __shared__ float sinv;
    if ((tid & 31) == 0) red[tid >> 5] = s;
    __syncthreads();
    if (tid == 0) {
        float t = 0.f;
        #pragma unroll
        for (int i = 0; i < 8; i++) t += red[i];
        sinv = 1.0f / fmaxf(sqrtf(t), 1e-8f);
    }
    __syncthreads();
    float inv = sinv;
    __half2* o1 = (__half2*)(d_gh + (size_t)g * DD);
    o1[2*tid]   = __floats2half2_rn(x.x * inv, x.y * inv);
    o1[2*tid+1] = __floats2half2_rn(x.z * inv, x.w * inv);
}

// ---------------- transpose guid -> fp16 [d][g] ----------------
__global__ void k_gt(const float* __restrict__ guid) {
    __shared__ float tile[32][33];
    int d0 = blockIdx.x * 32, g0 = blockIdx.y * 32;
    int tx = threadIdx.x, ty = threadIdx.y;
    #pragma unroll
    for (int yy = ty; yy < 32; yy += 8)
        tile[yy][tx] = guid[(size_t)(g0 + yy) * DD + (d0 + tx)];
    __syncthreads();
    #pragma unroll
    for (int yy = ty; yy < 32; yy += 8)
        d_gth[(size_t)(d0 + yy) * GG + (g0 + tx)] = __float2half_rn(tile[tx][yy]);
}

// ---------------- diffs -> normed (fp16), mags, zero sums ----------------
__global__ void __launch_bounds__(256) k_prep(const float* __restrict__ emb) {
    int lane = threadIdx.x & 31, wid = threadIdx.x >> 5;
    int r = blockIdx.x * 8 + wid;
    if (lane == 0) d_sums[r] = 0.f;
    __half2* nb = (__half2*)(d_nh + (size_t)r * DD);
    if (r >= ND) {
        __half2 z = __floats2half2_rn(0.f, 0.f);
        #pragma unroll
        for (int it = 0; it < 8; it++) {
            int v = lane + 32 * it;
            nb[2*v] = z; nb[2*v+1] = z;
        }
        if (lane == 0) d_mw[r] = 0.f;
        return;
    }
    int b = r / SDIFF;
    int i = r - b * SDIFF;
    const float4* e0 = (const float4*)(emb + ((size_t)b * SS + i) * DD);
    float4 df[8];
    float ssq = 0.f;
    #pragma unroll
    for (int it = 0; it < 8; it++) {
        int v = lane + 32 * it;
        float4 a = e0[v + DD/4];
        float4 c = e0[v];
        df[it].x = a.x - c.x; df[it].y = a.y - c.y;
        df[it].z = a.z - c.z; df[it].w = a.w - c.w;
        ssq += df[it].x*df[it].x + df[it].y*df[it].y + df[it].z*df[it].z + df[it].w*df[it].w;
    }
    #pragma unroll
    for (int o = 16; o; o >>= 1) ssq += __shfl_xor_sync(0xffffffffu, ssq, o);
    float mag = sqrtf(ssq);
    float scale = (mag > 1e-6f) ? (1.0f / mag) : 0.0f;
    if (lane == 0) d_mw[r] = tanhf(2.0f * mag);
    #pragma unroll
    for (int it = 0; it < 8; it++) {
        int v = lane + 32 * it;
        nb[2*v]   = __floats2half2_rn(df[it].x * scale, df[it].y * scale);
        nb[2*v+1] = __floats2half2_rn(df[it].z * scale, df[it].w * scale);
    }
}

// ---------------- mm1: sims = normed x gh^T (fp16) + exp epilogue ----------------
// grid (64, 2), 512 thr. CTA 128m x 256n, K=1024 in 16 chunks of 64. 3-stage.
__global__ void __launch_bounds__(512, 1) k_mm1() {
    extern __shared__ __align__(128) char smem[];
    uint32_t sbase = smem_u32(smem);
    int tid = threadIdx.x, wid = tid >> 5;
    int wm = wid >> 2, wn = wid & 3;
    int m0 = blockIdx.x * 128, n0 = blockIdx.y * 256;

    wmma::fragment<wmma::accumulator, 16, 16, 16, float> acc[2][4];
    #pragma unroll
    for (int mi = 0; mi < 2; mi++)
        #pragma unroll
        for (int ni = 0; ni < 4; ni++)
            wmma::fill_fragment(acc[mi][ni], 0.0f);

    auto load_chunk = [&](int kc, int buf) {
        uint32_t ab = sbase + buf * BUF1;
        #pragma unroll
        for (int i = 0; i < 2; i++) {
            int q = tid + i * 512;
            int r = q >> 3, v = q & 7;
            const char* src = (const char*)d_nh + ((size_t)(m0 + r) * DD + kc * 64 + v * 8) * 2;
            CP_ASYNC16(ab + r * 144 + v * 16, src);
        }
        uint32_t bb = ab + 18432;
        #pragma unroll
        for (int i = 0; i < 4; i++) {
            int q = tid + i * 512;
            int r = q >> 3, v = q & 7;
            const char* src = (const char*)d_gh + ((size_t)(n0 + r) * DD + kc * 64 + v * 8) * 2;
            CP_ASYNC16(bb + r * 144 + v * 16, src);
        }
        CP_COMMIT();
    };

    load_chunk(0, 0);
    load_chunk(1, 1);
    for (int kc = 0; kc < 16; kc++) {
        CP_WAIT1();
        __syncthreads();
        if (kc + 2 < 16) load_chunk(kc + 2, (kc + 2) % 3);
        const __half* As = (const __half*)(smem + (kc % 3) * BUF1);
        const __half* Bs = As + 9216;
        #pragma unroll
        for (int ks = 0; ks < 4; ks++) {
            wmma::fragment<wmma::matrix_a, 16, 16, 16, __half, wmma::row_major> af[2];
            wmma::fragment<wmma::matrix_b, 16, 16, 16, __half, wmma::col_major> bf[4];
            #pragma unroll
            for (int mi = 0; mi < 2; mi++)
                wmma::load_matrix_sync(af[mi], As + (wm*32 + mi*16) * LDA1 + ks*16, LDA1);
            #pragma unroll
            for (int ni = 0; ni < 4; ni++)
                wmma::load_matrix_sync(bf[ni], Bs + (wn*64 + ni*16) * LDA1 + ks*16, LDA1);
            #pragma unroll
            for (int mi = 0; mi < 2; mi++)
                #pragma unroll
                for (int ni = 0; ni < 4; ni++)
                    wmma::mma_sync(acc[mi][ni], af[mi], bf[ni], acc[mi][ni]);
        }
    }
    CP_WAIT0();
    __syncthreads();
    float* Cs = (float*)smem;   // [128][LDC1]
    #pragma unroll
    for (int mi = 0; mi < 2; mi++)
        #pragma unroll
        for (int ni = 0; ni < 4; ni++)
            wmma::store_matrix_sync(Cs + (wm*32 + mi*16) * LDC1 + wn*64 + ni*16,
                                    acc[mi][ni], LDC1, wmma::mem_row_major);
    __syncthreads();

    int row = tid >> 2, c0 = (tid & 3) * 64;
    float sum = 0.f;
    __half2* wout = (__half2*)(d_wh + (size_t)(m0 + row) * GG + n0 + c0);
    #pragma unroll 4
    for (int j = 0; j < 64; j += 4) {
        float e0 = __expf(2.0f * Cs[row * LDC1 + c0 + j + 0]);
        float e1 = __expf(2.0f * Cs[row * LDC1 + c0 + j + 1]);
        float e2 = __expf(2.0f * Cs[row * LDC1 + c0 + j + 2]);
        float e3 = __expf(2.0f * Cs[row * LDC1 + c0 + j + 3]);
        sum += e0 + e1 + e2 + e3;
        wout[(j >> 1) + 0] = __floats2half2_rn(e0, e1);
        wout[(j >> 1) + 1] = __floats2half2_rn(e2, e3);
    }
    atomicAdd(&d_sums[m0 + row], sum);
}

// ---------------- mm2: influence = wh x gth^T (fp16) + blend epilogue ----------------
// grid (64, 4), 512 thr. CTA 128m x 256d, K=512 in 8 chunks of 64. 3-stage.
__global__ void __launch_bounds__(512, 1) k_mm2() {
    extern __shared__ __align__(128) char smem[];
    uint32_t sbase = smem_u32(smem);
    int tid = threadIdx.x, wid = tid >> 5;
    int wm = wid >> 2, wn = wid & 3;
    int m0 = blockIdx.x * 128, n0 = blockIdx.y * 256;

    wmma::fragment<wmma::accumulator, 16, 16, 16, float> acc[2][4];
    #pragma unroll
    for (int mi = 0; mi < 2; mi++)
        #pragma unroll
        for (int ni = 0; ni < 4; ni++)
            wmma::fill_fragment(acc[mi][ni], 0.0f);

    auto load_chunk = [&](int kc, int buf) {
        uint32_t ab = sbase + buf * BUF1;
        #pragma unroll
        for (int i = 0; i < 2; i++) {
            int q = tid + i * 512;
            int r = q >> 3, v = q & 7;
            const char* src = (const char*)d_wh + ((size_t)(m0 + r) * GG + kc * 64 + v * 8) * 2;
            CP_ASYNC16(ab + r * 144 + v * 16, src);
        }
        uint32_t bb = ab + 18432;
        #pragma unroll
        for (int i = 0; i < 4; i++) {
            int q = tid + i * 512;
            int r = q >> 3, v = q & 7;
            const char* src = (const char*)d_gth + ((size_t)(n0 + r) * GG + kc * 64 + v * 8) * 2;
            CP_ASYNC16(bb + r * 144 + v * 16, src);
        }
        CP_COMMIT();
    };

    load_chunk(0, 0);
    load_chunk(1, 1);
    for (int kc = 0; kc < 8; kc++) {
        CP_WAIT1();
        __syncthreads();
        if (kc + 2 < 8) load_chunk(kc + 2, (kc + 2) % 3);
        const __half* As = (const __half*)(smem + (kc % 3) * BUF1);
        const __half* Bs = As + 9216;
        #pragma unroll
        for (int ks = 0; ks < 4; ks++) {
            wmma::fragment<wmma::matrix_a, 16, 16, 16, __half, wmma::row_major> af[2];
            wmma::fragment<wmma::matrix_b, 16, 16, 16, __half, wmma::col_major> bf[4];
            #pragma unroll
            for (int mi = 0; mi < 2; mi++)
                wmma::load_matrix_sync(af[mi], As + (wm*32 + mi*16) * LDA1 + ks*16, LDA1);
            #pragma unroll
            for (int ni = 0; ni < 4; ni++)
                wmma::load_matrix_sync(bf[ni], Bs + (wn*64 + ni*16) * LDA1 + ks*16, LDA1);
            #pragma unroll
            for (int mi = 0; mi < 2; mi++)
                #pragma unroll
                for (int ni = 0; ni < 4; ni++)
                    wmma::mma_sync(acc[mi][ni], af[mi], bf[ni], acc[mi][ni]);
        }
    }
    CP_WAIT0();
    __syncthreads();
    float* Cs = (float*)smem;   // [128][LDC1]
    #pragma unroll
    for (int mi = 0; mi < 2; mi++)
        #pragma unroll
        for (int ni = 0; ni < 4; ni++)
            wmma::store_matrix_sync(Cs + (wm*32 + mi*16) * LDC1 + wn*64 + ni*16,
                                    acc[mi][ni], LDC1, wmma::mem_row_major);
    __syncthreads();

    int row = tid >> 2, c0 = (tid & 3) * 64;
    int r = m0 + row;
    if (r < ND) {
        float sc = 0.4f / d_sums[r];
        const __half2* nh2 = (const __half2*)(d_nh + (size_t)r * DD + n0 + c0);
        float4* ob = (float4*)(d_blended + (size_t)r * DD + n0 + c0);
        #pragma unroll 4
        for (int j = 0; j < 16; j++) {
            float4 c = *(const float4*)&Cs[row * LDC1 + c0 + j * 4];
            float2 f0 = __half22float2(nh2[2*j]);
            float2 f1 = __half22float2(nh2[2*j+1]);
            float4 o;
            o.x = 0.6f * f0.x + sc * c.x;
            o.y = 0.6f * f0.y + sc * c.y;
            o.z = 0.6f * f1.x + sc * c.z;
            o.w = 0.6f * f1.y + sc * c.w;
            ob[j] = o;
        }
    }
}

// ---------------- windowed weighted blend into output (smem tap-reuse) ----------------
// grid (256, 4): x = 32-position group (4 batches x 64 groups), y = 256-float d-slice.
__global__ void __launch_bounds__(256) k_out(float* __restrict__ out) {
    __shared__ float4 sm[39][64];
    __shared__ float smw[39];
    int tid = threadIdx.x;
    int b = blockIdx.x >> 6;
    int p0 = (blockIdx.x & 63) * 32;
    int base = b * SDIFF;
    int dbase = blockIdx.y * 64;       // in float4 units

    // stage 39 blended row-slices + mw taps (rows p0-8 .. p0+30, clamped)
    #pragma unroll
    for (int i = 0; i < 10; i++) {
        int q = tid + i * 256;
        if (q < 39 * 64) {
            int j = q >> 6, col = q & 63;
            int rr = p0 - 8 + j;
            int gr = base + (rr < 0 ? 0 : rr);
            sm[j][col] = ((const float4*)d_blended)[(size_t)gr * 256 + dbase + col];
        }
    }
    if (tid < 39) {
        int rr = p0 - 8 + tid;
        smw[tid] = d_mw[base + (rr < 0 ? 0 : rr)];
    }
    __syncthreads();

    #pragma unroll
    for (int i = 0; i < 8; i++) {
        int item = i * 256 + tid;
        int pl = item >> 6, col = item & 63;
        int p = p0 + pl;
        float c[WW];
        float wsum = 0.f;
        #pragma unroll
        for (int k = 0; k < WW; k++) {
            int idx = p - WW + k;
            float ck = 0.f;
            if (p >= 1 && idx >= 0) {
                int w = (p < WW) ? p : WW;
                int j = k - (WW - w);
                float lin = (w > 1) ? (0.1f + 0.9f * (float)j / (float)(w - 1)) : 0.1f;
                ck = lin * smw[pl + k];
            }
            c[k] = ck;
            wsum += ck;
        }
        float inv = 1.0f / fmaxf(wsum, 1e-8f);
        float4 o = make_float4(0.f, 0.f, 0.f, 0.f);
        #pragma unroll
        for (int k = 0; k < WW; k++) {
            if (c[k] != 0.f) {
                float4 v = sm[pl + k][col];
                o.x = fmaf(c[k], v.x, o.x);
                o.y = fmaf(c[k], v.y, o.y);
                o.z = fmaf(c[k], v.z, o.z);
                o.w = fmaf(c[k], v.w, o.w);
            }
        }
        o.x *= inv; o.y *= inv; o.z *= inv; o.w *= inv;
        ((float4*)out)[(size_t)(b * SS + p) * 256 + dbase + col] = o;
    }
}

extern "C" void kernel_launch(void* const* d_in, const int* in_sizes, int n_in,
                              void* d_out, int out_size) {
    (void)in_sizes; (void)n_in; (void)out_size;
    const float* emb  = (const float*)d_in[0];
    const float* guid = (const float*)d_in[1];
    float* out = (float*)d_out;

    cudaFuncSetAttribute(k_mm1, cudaFuncAttributeMaxDynamicSharedMemorySize, SMEM1);
    cudaFuncSetAttribute(k_mm2, cudaFuncAttributeMaxDynamicSharedMemorySize, SMEM1);

    k_gprep<<<GG, 256>>>(guid);
    k_gt<<<dim3(DD/32, GG/32), dim3(32, 8)>>>(guid);
    k_prep<<<MPAD/8, 256>>>(emb);
    k_mm1<<<dim3(64, 2), 512, SMEM1>>>();
    k_mm2<<<dim3(64, 4), 512, SMEM1>>>();
    k_out<<<dim3(256, 4), 256>>>(out);
}

// round 12
// speedup vs baseline: 3.7963x; 1.0463x over previous
#include <cuda_runtime.h>
#include <cuda_fp16.h>
#include <mma.h>
#include <cstdint>
#include <math.h>

using namespace nvcuda;

#define BB 4
#define SS 2048
#define DD 1024
#define GG 512
#define WW 8
#define SDIFF 2047
#define ND (BB*SDIFF)            // 8188
#define MPAD 8192

// GEMMs: fp16, CTA 128m x 256n, 256 thr (8 warps, warp tile 64x64), K-chunk 64, 3-stage.
#define LDA1 72                  // fp16 elems (144B rows)
#define BUF1 55296               // 128*144 + 256*144
#define LDC1 260
#define SMEM1 165888             // 3*BUF1 (> epilogue 128*260*4=133120)

#define CP_ASYNC16(dst, src) \
    asm volatile("cp.async.cg.shared.global [%0], [%1], 16;" :: "r"(dst), "l"(src))
#define CP_COMMIT() asm volatile("cp.async.commit_group;" ::: "memory")
#define CP_WAIT1() asm volatile("cp.async.wait_group 1;" ::: "memory")
#define CP_WAIT0() asm volatile("cp.async.wait_group 0;" ::: "memory")

__device__ __forceinline__ uint32_t smem_u32(const void* p) {
    uint32_t a;
    asm("{ .reg .u64 t; cvta.to.shared.u64 t, %1; cvt.u32.u64 %0, t; }" : "=r"(a) : "l"(p));
    return a;
}

// ---------------- global scratch ----------------
__device__ __half  d_gh[GG * DD];              // guid/||g|| fp16 [g][k]
__device__ __half  d_gth[DD * GG];             // guid^T fp16 [d][g]
__device__ __half  d_nh[(size_t)MPAD * DD];    // normed fp16 [r][k]
__device__ float   d_mw[MPAD];                 // tanh(2*mag)
__device__ __half  d_wh[(size_t)MPAD * GG];    // exp(2*sims) fp16 [r][g]
__device__ float   d_sums[MPAD];               // row sums of exp (f32)
__device__ float   d_blended[(size_t)MPAD * DD];

// ---------------- guidance: norm + fp16 normalized [g][k] ----------------
__global__ void k_gprep(const float* __restrict__ guid) {
    int g = blockIdx.x, tid = threadIdx.x;
    const float4* row = (const float4*)(guid + (size_t)g * DD);
    float4 x = row[tid];
    float s = x.x*x.x + x.y*x.y + x.z*x.z + x.w*x.w;
    #pragma unroll
    for (int o = 16; o; o >>= 1) s += __shfl_xor_sync(0xffffffffu, s, o);
    __shared__ float red[8];
    __shared__ float sinv;
    if ((tid & 31) == 0) red[tid >> 5] = s;
    __syncthreads();
    if (tid == 0) {
        float t = 0.f;
        #pragma unroll
        for (int i = 0; i < 8; i++) t += red[i];
        sinv = 1.0f / fmaxf(sqrtf(t), 1e-8f);
    }
    __syncthreads();
    float inv = sinv;
    __half2* o1 = (__half2*)(d_gh + (size_t)g * DD);
    o1[2*tid]   = __floats2half2_rn(x.x * inv, x.y * inv);
    o1[2*tid+1] = __floats2half2_rn(x.z * inv, x.w * inv);
}

// ---------------- transpose guid -> fp16 [d][g] ----------------
__global__ void k_gt(const float* __restrict__ guid) {
    __shared__ float tile[32][33];
    int d0 = blockIdx.x * 32, g0 = blockIdx.y * 32;
    int tx = threadIdx.x, ty = threadIdx.y;
    #pragma unroll
    for (int yy = ty; yy < 32; yy += 8)
        tile[yy][tx] = guid[(size_t)(g0 + yy) * DD + (d0 + tx)];
    __syncthreads();
    #pragma unroll
    for (int yy = ty; yy < 32; yy += 8)
        d_gth[(size_t)(d0 + yy) * GG + (g0 + tx)] = __float2half_rn(tile[tx][yy]);
}

// ---------------- diffs -> normed (fp16), mags, zero sums ----------------
__global__ void __launch_bounds__(256) k_prep(const float* __restrict__ emb) {
    int lane = threadIdx.x & 31, wid = threadIdx.x >> 5;
    int r = blockIdx.x * 8 + wid;
    if (lane == 0) d_sums[r] = 0.f;
    __half2* nb = (__half2*)(d_nh + (size_t)r * DD);
    if (r >= ND) {
        __half2 z = __floats2half2_rn(0.f, 0.f);
        #pragma unroll
        for (int it = 0; it < 8; it++) {
            int v = lane + 32 * it;
            nb[2*v] = z; nb[2*v+1] = z;
        }
        if (lane == 0) d_mw[r] = 0.f;
        return;
    }
    int b = r / SDIFF;
    int i = r - b * SDIFF;
    const float4* e0 = (const float4*)(emb + ((size_t)b * SS + i) * DD);
    float4 df[8];
    float ssq = 0.f;
    #pragma unroll
    for (int it = 0; it < 8; it++) {
        int v = lane + 32 * it;
        float4 a = e0[v + DD/4];
        float4 c = e0[v];
        df[it].x = a.x - c.x; df[it].y = a.y - c.y;
        df[it].z = a.z - c.z; df[it].w = a.w - c.w;
        ssq += df[it].x*df[it].x + df[it].y*df[it].y + df[it].z*df[it].z + df[it].w*df[it].w;
    }
    #pragma unroll
    for (int o = 16; o; o >>= 1) ssq += __shfl_xor_sync(0xffffffffu, ssq, o);
    float mag = sqrtf(ssq);
    float scale = (mag > 1e-6f) ? (1.0f / mag) : 0.0f;
    if (lane == 0) d_mw[r] = tanhf(2.0f * mag);
    #pragma unroll
    for (int it = 0; it < 8; it++) {
        int v = lane + 32 * it;
        nb[2*v]   = __floats2half2_rn(df[it].x * scale, df[it].y * scale);
        nb[2*v+1] = __floats2half2_rn(df[it].z * scale, df[it].w * scale);
    }
}

// ---------------- mm1: sims = normed x gh^T (fp16) + exp epilogue ----------------
// grid (64, 2), 256 thr (8 warps, 2m x 4n of 64x64). K=1024 in 16 chunks of 64. 3-stage.
__global__ void __launch_bounds__(256, 1) k_mm1() {
    extern __shared__ __align__(128) char smem[];
    uint32_t sbase = smem_u32(smem);
    int tid = threadIdx.x, wid = tid >> 5;
    int wm = wid >> 2, wn = wid & 3;
    int m0 = blockIdx.x * 128, n0 = blockIdx.y * 256;

    wmma::fragment<wmma::accumulator, 16, 16, 16, float> acc[4][4];
    #pragma unroll
    for (int mi = 0; mi < 4; mi++)
        #pragma unroll
        for (int ni = 0; ni < 4; ni++)
            wmma::fill_fragment(acc[mi][ni], 0.0f);

    auto load_chunk = [&](int kc, int buf) {
        uint32_t ab = sbase + buf * BUF1;
        #pragma unroll
        for (int i = 0; i < 4; i++) {
            int q = tid + i * 256;
            int r = q >> 3, v = q & 7;
            const char* src = (const char*)d_nh + ((size_t)(m0 + r) * DD + kc * 64 + v * 8) * 2;
            CP_ASYNC16(ab + r * 144 + v * 16, src);
        }
        uint32_t bb = ab + 18432;
        #pragma unroll
        for (int i = 0; i < 8; i++) {
            int q = tid + i * 256;
            int r = q >> 3, v = q & 7;
            const char* src = (const char*)d_gh + ((size_t)(n0 + r) * DD + kc * 64 + v * 8) * 2;
            CP_ASYNC16(bb + r * 144 + v * 16, src);
        }
        CP_COMMIT();
    };

    load_chunk(0, 0);
    load_chunk(1, 1);
    for (int kc = 0; kc < 16; kc++) {
        CP_WAIT1();
        __syncthreads();
        if (kc + 2 < 16) load_chunk(kc + 2, (kc + 2) % 3);
        const __half* As = (const __half*)(smem + (kc % 3) * BUF1);
        const __half* Bs = As + 9216;
        #pragma unroll
        for (int ks = 0; ks < 4; ks++) {
            wmma::fragment<wmma::matrix_a, 16, 16, 16, __half, wmma::row_major> af[4];
            wmma::fragment<wmma::matrix_b, 16, 16, 16, __half, wmma::col_major> bf[4];
            #pragma unroll
            for (int mi = 0; mi < 4; mi++)
                wmma::load_matrix_sync(af[mi], As + (wm*64 + mi*16) * LDA1 + ks*16, LDA1);
            #pragma unroll
            for (int ni = 0; ni < 4; ni++)
                wmma::load_matrix_sync(bf[ni], Bs + (wn*64 + ni*16) * LDA1 + ks*16, LDA1);
            #pragma unroll
            for (int mi = 0; mi < 4; mi++)
                #pragma unroll
                for (int ni = 0; ni < 4; ni++)
                    wmma::mma_sync(acc[mi][ni], af[mi], bf[ni], acc[mi][ni]);
        }
    }
    CP_WAIT0();
    __syncthreads();
    float* Cs = (float*)smem;   // [128][LDC1]
    #pragma unroll
    for (int mi = 0; mi < 4; mi++)
        #pragma unroll
        for (int ni = 0; ni < 4; ni++)
            wmma::store_matrix_sync(Cs + (wm*64 + mi*16) * LDC1 + wn*64 + ni*16,
                                    acc[mi][ni], LDC1, wmma::mem_row_major);
    __syncthreads();

    int row = tid >> 1, c0 = (tid & 1) * 128;
    float sum = 0.f;
    __half2* wout = (__half2*)(d_wh + (size_t)(m0 + row) * GG + n0 + c0);
    #pragma unroll 8
    for (int j = 0; j < 128; j += 4) {
        float e0 = __expf(2.0f * Cs[row * LDC1 + c0 + j + 0]);
        float e1 = __expf(2.0f * Cs[row * LDC1 + c0 + j + 1]);
        float e2 = __expf(2.0f * Cs[row * LDC1 + c0 + j + 2]);
        float e3 = __expf(2.0f * Cs[row * LDC1 + c0 + j + 3]);
        sum += e0 + e1 + e2 + e3;
        wout[(j >> 1) + 0] = __floats2half2_rn(e0, e1);
        wout[(j >> 1) + 1] = __floats2half2_rn(e2, e3);
    }
    atomicAdd(&d_sums[m0 + row], sum);
}

// ---------------- mm2: influence = wh x gth^T (fp16) + blend epilogue ----------------
// grid (64, 4), 256 thr (8 warps, 2m x 4n of 64x64). K=512 in 8 chunks of 64. 3-stage.
__global__ void __launch_bounds__(256, 1) k_mm2() {
    extern __shared__ __align__(128) char smem[];
    uint32_t sbase = smem_u32(smem);
    int tid = threadIdx.x, wid = tid >> 5;
    int wm = wid >> 2, wn = wid & 3;
    int m0 = blockIdx.x * 128, n0 = blockIdx.y * 256;

    wmma::fragment<wmma::accumulator, 16, 16, 16, float> acc[4][4];
    #pragma unroll
    for (int mi = 0; mi < 4; mi++)
        #pragma unroll
        for (int ni = 0; ni < 4; ni++)
            wmma::fill_fragment(acc[mi][ni], 0.0f);

    auto load_chunk = [&](int kc, int buf) {
        uint32_t ab = sbase + buf * BUF1;
        #pragma unroll
        for (int i = 0; i < 4; i++) {
            int q = tid + i * 256;
            int r = q >> 3, v = q & 7;
            const char* src = (const char*)d_wh + ((size_t)(m0 + r) * GG + kc * 64 + v * 8) * 2;
            CP_ASYNC16(ab + r * 144 + v * 16, src);
        }
        uint32_t bb = ab + 18432;
        #pragma unroll
        for (int i = 0; i < 8; i++) {
            int q = tid + i * 256;
            int r = q >> 3, v = q & 7;
            const char* src = (const char*)d_gth + ((size_t)(n0 + r) * GG + kc * 64 + v * 8) * 2;
            CP_ASYNC16(bb + r * 144 + v * 16, src);
        }
        CP_COMMIT();
    };

    load_chunk(0, 0);
    load_chunk(1, 1);
    for (int kc = 0; kc < 8; kc++) {
        CP_WAIT1();
        __syncthreads();
        if (kc + 2 < 8) load_chunk(kc + 2, (kc + 2) % 3);
        const __half* As = (const __half*)(smem + (kc % 3) * BUF1);
        const __half* Bs = As + 9216;
        #pragma unroll
        for (int ks = 0; ks < 4; ks++) {
            wmma::fragment<wmma::matrix_a, 16, 16, 16, __half, wmma::row_major> af[4];
            wmma::fragment<wmma::matrix_b, 16, 16, 16, __half, wmma::col_major> bf[4];
            #pragma unroll
            for (int mi = 0; mi < 4; mi++)
                wmma::load_matrix_sync(af[mi], As + (wm*64 + mi*16) * LDA1 + ks*16, LDA1);
            #pragma unroll
            for (int ni = 0; ni < 4; ni++)
                wmma::load_matrix_sync(bf[ni], Bs + (wn*64 + ni*16) * LDA1 + ks*16, LDA1);
            #pragma unroll
            for (int mi = 0; mi < 4; mi++)
                #pragma unroll
                for (int ni = 0; ni < 4; ni++)
                    wmma::mma_sync(acc[mi][ni], af[mi], bf[ni], acc[mi][ni]);
        }
    }
    CP_WAIT0();
    __syncthreads();
    float* Cs = (float*)smem;   // [128][LDC1]
    #pragma unroll
    for (int mi = 0; mi < 4; mi++)
        #pragma unroll
        for (int ni = 0; ni < 4; ni++)
            wmma::store_matrix_sync(Cs + (wm*64 + mi*16) * LDC1 + wn*64 + ni*16,
                                    acc[mi][ni], LDC1, wmma::mem_row_major);
    __syncthreads();

    int row = tid >> 1, c0 = (tid & 1) * 128;
    int r = m0 + row;
    if (r < ND) {
        float sc = 0.4f / d_sums[r];
        const __half2* nh2 = (const __half2*)(d_nh + (size_t)r * DD + n0 + c0);
        float4* ob = (float4*)(d_blended + (size_t)r * DD + n0 + c0);
        #pragma unroll 8
        for (int j = 0; j < 32; j++) {
            float4 c = *(const float4*)&Cs[row * LDC1 + c0 + j * 4];
            float2 f0 = __half22float2(nh2[2*j]);
            float2 f1 = __half22float2(nh2[2*j+1]);
            float4 o;
            o.x = 0.6f * f0.x + sc * c.x;
            o.y = 0.6f * f0.y + sc * c.y;
            o.z = 0.6f * f1.x + sc * c.z;
            o.w = 0.6f * f1.y + sc * c.w;
            ob[j] = o;
        }
    }
}

// ---------------- windowed weighted blend into output (smem tap-reuse) ----------------
// grid (256, 4): x = 32-position group (4 batches x 64 groups), y = 256-float d-slice.
__global__ void __launch_bounds__(256) k_out(float* __restrict__ out) {
    __shared__ float4 sm[39][64];
    __shared__ float smw[39];
    int tid = threadIdx.x;
    int b = blockIdx.x >> 6;
    int p0 = (blockIdx.x & 63) * 32;
    int base = b * SDIFF;
    int dbase = blockIdx.y * 64;       // in float4 units

    #pragma unroll
    for (int i = 0; i < 10; i++) {
        int q = tid + i * 256;
        if (q < 39 * 64) {
            int j = q >> 6, col = q & 63;
            int rr = p0 - 8 + j;
            int gr = base + (rr < 0 ? 0 : rr);
            sm[j][col] = ((const float4*)d_blended)[(size_t)gr * 256 + dbase + col];
        }
    }
    if (tid < 39) {
        int rr = p0 - 8 + tid;
        smw[tid] = d_mw[base + (rr < 0 ? 0 : rr)];
    }
    __syncthreads();

    #pragma unroll
    for (int i = 0; i < 8; i++) {
        int item = i * 256 + tid;
        int pl = item >> 6, col = item & 63;
        int p = p0 + pl;
        float c[WW];
        float wsum = 0.f;
        #pragma unroll
        for (int k = 0; k < WW; k++) {
            int idx = p - WW + k;
            float ck = 0.f;
            if (p >= 1 && idx >= 0) {
                int w = (p < WW) ? p : WW;
                int j = k - (WW - w);
                float lin = (w > 1) ? (0.1f + 0.9f * (float)j / (float)(w - 1)) : 0.1f;
                ck = lin * smw[pl + k];
            }
            c[k] = ck;
            wsum += ck;
        }
        float inv = 1.0f / fmaxf(wsum, 1e-8f);
        float4 o = make_float4(0.f, 0.f, 0.f, 0.f);
        #pragma unroll
        for (int k = 0; k < WW; k++) {
            if (c[k] != 0.f) {
                float4 v = sm[pl + k][col];
                o.x = fmaf(c[k], v.x, o.x);
                o.y = fmaf(c[k], v.y, o.y);
                o.z = fmaf(c[k], v.z, o.z);
                o.w = fmaf(c[k], v.w, o.w);
            }
        }
        o.x *= inv; o.y *= inv; o.z *= inv; o.w *= inv;
        ((float4*)out)[(size_t)(b * SS + p) * 256 + dbase + col] = o;
    }
}

extern "C" void kernel_launch(void* const* d_in, const int* in_sizes, int n_in,
                              void* d_out, int out_size) {
    (void)in_sizes; (void)n_in; (void)out_size;
    const float* emb  = (const float*)d_in[0];
    const float* guid = (const float*)d_in[1];
    float* out = (float*)d_out;

    cudaFuncSetAttribute(k_mm1, cudaFuncAttributeMaxDynamicSharedMemorySize, SMEM1);
    cudaFuncSetAttribute(k_mm2, cudaFuncAttributeMaxDynamicSharedMemorySize, SMEM1);

    k_gprep<<<GG, 256>>>(guid);
    k_gt<<<dim3(DD/32, GG/32), dim3(32, 8)>>>(guid);
    k_prep<<<MPAD/8, 256>>>(emb);
    k_mm1<<<dim3(64, 2), 256, SMEM1>>>();
    k_mm2<<<dim3(64, 4), 256, SMEM1>>>();
    k_out<<<dim3(256, 4), 256>>>(out);
}

// round 13
// speedup vs baseline: 3.9201x; 1.0326x over previous
#include <cuda_runtime.h>
#include <cuda_fp16.h>
#include <mma.h>
#include <cstdint>
#include <math.h>

using namespace nvcuda;

#define BB 4
#define SS 2048
#define DD 1024
#define GG 512
#define WW 8
#define SDIFF 2047
#define ND (BB*SDIFF)            // 8188
#define MPAD 8192

// GEMMs: fp16, CTA 128m x 256n, 256 thr (8 warps, warp tile 64x64), K-chunk 64, 3-stage.
#define LDA1 72                  // fp16 elems (144B rows)
#define BUF1 55296               // 128*144 + 256*144
#define LDC1 260
#define SMEM1 165888             // 3*BUF1 (> epilogue 128*260*4=133120)

#define CP_ASYNC16(dst, src) \
    asm volatile("cp.async.cg.shared.global [%0], [%1], 16;" :: "r"(dst), "l"(src))
#define CP_COMMIT() asm volatile("cp.async.commit_group;" ::: "memory")
#define CP_WAIT1() asm volatile("cp.async.wait_group 1;" ::: "memory")
#define CP_WAIT0() asm volatile("cp.async.wait_group 0;" ::: "memory")

__device__ __forceinline__ uint32_t smem_u32(const void* p) {
    uint32_t a;
    asm("{ .reg .u64 t; cvta.to.shared.u64 t, %1; cvt.u32.u64 %0, t; }" : "=r"(a) : "l"(p));
    return a;
}

// ---------------- global scratch ----------------
__device__ __half  d_gh[GG * DD];              // guid/||g|| fp16 [g][k]
__device__ __half  d_gth[DD * GG];             // guid^T fp16 [d][g]
__device__ __half  d_nh[(size_t)MPAD * DD];    // normed fp16 [r][k]
__device__ float   d_mw[MPAD];                 // tanh(2*mag)
__device__ __half  d_wh[(size_t)MPAD * GG];    // exp(2*sims) fp16 [r][g]
__device__ float   d_sums[MPAD];               // row sums of exp (f32)
__device__ __half  d_blh[(size_t)MPAD * DD];   // blended fp16 [r][d]

// ---------------- fused prep: gprep (512) + gt (512) + diff-prep (1024) ----------------
__global__ void __launch_bounds__(256) k_fused(const float* __restrict__ emb,
                                               const float* __restrict__ guid) {
    int bid = blockIdx.x;
    int tid = threadIdx.x;
    if (bid < 512) {
        // --- gprep: norm + fp16 normalized [g][k] ---
        int g = bid;
        const float4* row = (const float4*)(guid + (size_t)g * DD);
        float4 x = row[tid];
        float s = x.x*x.x + x.y*x.y + x.z*x.z + x.w*x.w;
        #pragma unroll
        for (int o = 16; o; o >>= 1) s += __shfl_xor_sync(0xffffffffu, s, o);
        __shared__ float red[8];
        __shared__ float sinv;
        if ((tid & 31) == 0) red[tid >> 5] = s;
        __syncthreads();
        if (tid == 0) {
            float t = 0.f;
            #pragma unroll
            for (int i = 0; i < 8; i++) t += red[i];
            sinv = 1.0f / fmaxf(sqrtf(t), 1e-8f);
        }
        __syncthreads();
        float inv = sinv;
        __half2* o1 = (__half2*)(d_gh + (size_t)g * DD);
        o1[2*tid]   = __floats2half2_rn(x.x * inv, x.y * inv);
        o1[2*tid+1] = __floats2half2_rn(x.z * inv, x.w * inv);
    } else if (bid < 1024) {
        // --- gt: transpose guid -> fp16 [d][g] ---
        __shared__ float tile[32][33];
        int lb = bid - 512;
        int d0 = (lb & 31) * 32, g0 = (lb >> 5) * 32;
        int tx = tid & 31, ty = tid >> 5;
        #pragma unroll
        for (int yy = ty; yy < 32; yy += 8)
            tile[yy][tx] = guid[(size_t)(g0 + yy) * DD + (d0 + tx)];
        __syncthreads();
        #pragma unroll
        for (int yy = ty; yy < 32; yy += 8)
            d_gth[(size_t)(d0 + yy) * GG + (g0 + tx)] = __float2half_rn(tile[tx][yy]);
    } else {
        // --- prep: diffs -> normed fp16, mags, zero sums ---
        int lane = tid & 31, wid = tid >> 5;
        int r = (bid - 1024) * 8 + wid;
        if (lane == 0) d_sums[r] = 0.f;
        __half2* nb = (__half2*)(d_nh + (size_t)r * DD);
        if (r >= ND) {
            __half2 z = __floats2half2_rn(0.f, 0.f);
            #pragma unroll
            for (int it = 0; it < 8; it++) {
                int v = lane + 32 * it;
                nb[2*v] = z; nb[2*v+1] = z;
            }
            if (lane == 0) d_mw[r] = 0.f;
            return;
        }
        int b = r / SDIFF;
        int i = r - b * SDIFF;
        const float4* e0 = (const float4*)(emb + ((size_t)b * SS + i) * DD);
        float4 df[8];
        float ssq = 0.f;
        #pragma unroll
        for (int it = 0; it < 8; it++) {
            int v = lane + 32 * it;
            float4 a = e0[v + DD/4];
            float4 c = e0[v];
            df[it].x = a.x - c.x; df[it].y = a.y - c.y;
            df[it].z = a.z - c.z; df[it].w = a.w - c.w;
            ssq += df[it].x*df[it].x + df[it].y*df[it].y + df[it].z*df[it].z + df[it].w*df[it].w;
        }
        #pragma unroll
        for (int o = 16; o; o >>= 1) ssq += __shfl_xor_sync(0xffffffffu, ssq, o);
        float mag = sqrtf(ssq);
        float scale = (mag > 1e-6f) ? (1.0f / mag) : 0.0f;
        if (lane == 0) d_mw[r] = tanhf(2.0f * mag);
        #pragma unroll
        for (int it = 0; it < 8; it++) {
            int v = lane + 32 * it;
            nb[2*v]   = __floats2half2_rn(df[it].x * scale, df[it].y * scale);
            nb[2*v+1] = __floats2half2_rn(df[it].z * scale, df[it].w * scale);
        }
    }
}

// ---------------- mm1: sims = normed x gh^T (fp16) + exp epilogue ----------------
// grid (64, 2), 256 thr (8 warps, 2m x 4n of 64x64). K=1024 in 16 chunks of 64. 3-stage.
__global__ void __launch_bounds__(256, 1) k_mm1() {
    extern __shared__ __align__(128) char smem[];
    uint32_t sbase = smem_u32(smem);
    int tid = threadIdx.x, wid = tid >> 5;
    int wm = wid >> 2, wn = wid & 3;
    int m0 = blockIdx.x * 128, n0 = blockIdx.y * 256;

    wmma::fragment<wmma::accumulator, 16, 16, 16, float> acc[4][4];
    #pragma unroll
    for (int mi = 0; mi < 4; mi++)
        #pragma unroll
        for (int ni = 0; ni < 4; ni++)
            wmma::fill_fragment(acc[mi][ni], 0.0f);

    auto load_chunk = [&](int kc, int buf) {
        uint32_t ab = sbase + buf * BUF1;
        #pragma unroll
        for (int i = 0; i < 4; i++) {
            int q = tid + i * 256;
            int r = q >> 3, v = q & 7;
            const char* src = (const char*)d_nh + ((size_t)(m0 + r) * DD + kc * 64 + v * 8) * 2;
            CP_ASYNC16(ab + r * 144 + v * 16, src);
        }
        uint32_t bb = ab + 18432;
        #pragma unroll
        for (int i = 0; i < 8; i++) {
            int q = tid + i * 256;
            int r = q >> 3, v = q & 7;
            const char* src = (const char*)d_gh + ((size_t)(n0 + r) * DD + kc * 64 + v * 8) * 2;
            CP_ASYNC16(bb + r * 144 + v * 16, src);
        }
        CP_COMMIT();
    };

    load_chunk(0, 0);
    load_chunk(1, 1);
    for (int kc = 0; kc < 16; kc++) {
        CP_WAIT1();
        __syncthreads();
        if (kc + 2 < 16) load_chunk(kc + 2, (kc + 2) % 3);
        const __half* As = (const __half*)(smem + (kc % 3) * BUF1);
        const __half* Bs = As + 9216;
        #pragma unroll
        for (int ks = 0; ks < 4; ks++) {
            wmma::fragment<wmma::matrix_a, 16, 16, 16, __half, wmma::row_major> af[4];
            wmma::fragment<wmma::matrix_b, 16, 16, 16, __half, wmma::col_major> bf[4];
            #pragma unroll
            for (int mi = 0; mi < 4; mi++)
                wmma::load_matrix_sync(af[mi], As + (wm*64 + mi*16) * LDA1 + ks*16, LDA1);
            #pragma unroll
            for (int ni = 0; ni < 4; ni++)
                wmma::load_matrix_sync(bf[ni], Bs + (wn*64 + ni*16) * LDA1 + ks*16, LDA1);
            #pragma unroll
            for (int mi = 0; mi < 4; mi++)
                #pragma unroll
                for (int ni = 0; ni < 4; ni++)
                    wmma::mma_sync(acc[mi][ni], af[mi], bf[ni], acc[mi][ni]);
        }
    }
    CP_WAIT0();
    __syncthreads();
    float* Cs = (float*)smem;   // [128][LDC1]
    #pragma unroll
    for (int mi = 0; mi < 4; mi++)
        #pragma unroll
        for (int ni = 0; ni < 4; ni++)
            wmma::store_matrix_sync(Cs + (wm*64 + mi*16) * LDC1 + wn*64 + ni*16,
                                    acc[mi][ni], LDC1, wmma::mem_row_major);
    __syncthreads();

    int row = tid >> 1, c0 = (tid & 1) * 128;
    float sum = 0.f;
    __half2* wout = (__half2*)(d_wh + (size_t)(m0 + row) * GG + n0 + c0);
    #pragma unroll 8
    for (int j = 0; j < 128; j += 4) {
        float e0 = __expf(2.0f * Cs[row * LDC1 + c0 + j + 0]);
        float e1 = __expf(2.0f * Cs[row * LDC1 + c0 + j + 1]);
        float e2 = __expf(2.0f * Cs[row * LDC1 + c0 + j + 2]);
        float e3 = __expf(2.0f * Cs[row * LDC1 + c0 + j + 3]);
        sum += e0 + e1 + e2 + e3;
        wout[(j >> 1) + 0] = __floats2half2_rn(e0, e1);
        wout[(j >> 1) + 1] = __floats2half2_rn(e2, e3);
    }
    atomicAdd(&d_sums[m0 + row], sum);
}

// ---------------- mm2: influence = wh x gth^T (fp16) + blend epilogue (fp16 out) ----------------
// grid (64, 4), 256 thr (8 warps, 2m x 4n of 64x64). K=512 in 8 chunks of 64. 3-stage.
__global__ void __launch_bounds__(256, 1) k_mm2() {
    extern __shared__ __align__(128) char smem[];
    uint32_t sbase = smem_u32(smem);
    int tid = threadIdx.x, wid = tid >> 5;
    int wm = wid >> 2, wn = wid & 3;
    int m0 = blockIdx.x * 128, n0 = blockIdx.y * 256;

    wmma::fragment<wmma::accumulator, 16, 16, 16, float> acc[4][4];
    #pragma unroll
    for (int mi = 0; mi < 4; mi++)
        #pragma unroll
        for (int ni = 0; ni < 4; ni++)
            wmma::fill_fragment(acc[mi][ni], 0.0f);

    auto load_chunk = [&](int kc, int buf) {
        uint32_t ab = sbase + buf * BUF1;
        #pragma unroll
        for (int i = 0; i < 4; i++) {
            int q = tid + i * 256;
            int r = q >> 3, v = q & 7;
            const char* src = (const char*)d_wh + ((size_t)(m0 + r) * GG + kc * 64 + v * 8) * 2;
            CP_ASYNC16(ab + r * 144 + v * 16, src);
        }
        uint32_t bb = ab + 18432;
        #pragma unroll
        for (int i = 0; i < 8; i++) {
            int q = tid + i * 256;
            int r = q >> 3, v = q & 7;
            const char* src = (const char*)d_gth + ((size_t)(n0 + r) * GG + kc * 64 + v * 8) * 2;
            CP_ASYNC16(bb + r * 144 + v * 16, src);
        }
        CP_COMMIT();
    };

    load_chunk(0, 0);
    load_chunk(1, 1);
    for (int kc = 0; kc < 8; kc++) {
        CP_WAIT1();
        __syncthreads();
        if (kc + 2 < 8) load_chunk(kc + 2, (kc + 2) % 3);
        const __half* As = (const __half*)(smem + (kc % 3) * BUF1);
        const __half* Bs = As + 9216;
        #pragma unroll
        for (int ks = 0; ks < 4; ks++) {
            wmma::fragment<wmma::matrix_a, 16, 16, 16, __half, wmma::row_major> af[4];
            wmma::fragment<wmma::matrix_b, 16, 16, 16, __half, wmma::col_major> bf[4];
            #pragma unroll
            for (int mi = 0; mi < 4; mi++)
                wmma::load_matrix_sync(af[mi], As + (wm*64 + mi*16) * LDA1 + ks*16, LDA1);
            #pragma unroll
            for (int ni = 0; ni < 4; ni++)
                wmma::load_matrix_sync(bf[ni], Bs + (wn*64 + ni*16) * LDA1 + ks*16, LDA1);
            #pragma unroll
            for (int mi = 0; mi < 4; mi++)
                #pragma unroll
                for (int ni = 0; ni < 4; ni++)
                    wmma::mma_sync(acc[mi][ni], af[mi], bf[ni], acc[mi][ni]);
        }
    }
    CP_WAIT0();
    __syncthreads();
    float* Cs = (float*)smem;   // [128][LDC1]
    #pragma unroll
    for (int mi = 0; mi < 4; mi++)
        #pragma unroll
        for (int ni = 0; ni < 4; ni++)
            wmma::store_matrix_sync(Cs + (wm*64 + mi*16) * LDC1 + wn*64 + ni*16,
                                    acc[mi][ni], LDC1, wmma::mem_row_major);
    __syncthreads();

    int row = tid >> 1, c0 = (tid & 1) * 128;
    int r = m0 + row;
    if (r < ND) {
        float sc = 0.4f / d_sums[r];
        const __half2* nh2 = (const __half2*)(d_nh + (size_t)r * DD + n0 + c0);
        uint2* ob = (uint2*)(d_blh + (size_t)r * DD + n0 + c0);
        #pragma unroll 8
        for (int j = 0; j < 32; j++) {
            float4 c = *(const float4*)&Cs[row * LDC1 + c0 + j * 4];
            float2 f0 = __half22float2(nh2[2*j]);
            float2 f1 = __half22float2(nh2[2*j+1]);
            __half2 h0 = __floats2half2_rn(0.6f * f0.x + sc * c.x, 0.6f * f0.y + sc * c.y);
            __half2 h1 = __floats2half2_rn(0.6f * f1.x + sc * c.z, 0.6f * f1.y + sc * c.w);
            uint2 u;
            u.x = *(uint32_t*)&h0;
            u.y = *(uint32_t*)&h1;
            ob[j] = u;
        }
    }
}

// ---------------- windowed weighted blend into output (fp16 smem tap-reuse) ----------------
// grid (256, 4): x = 32-position group (4 batches x 64 groups), y = 256-elem d-slice.
__global__ void __launch_bounds__(256) k_out(float* __restrict__ out) {
    __shared__ uint2 sm[39][64];      // 39 rows x 256 halves
    __shared__ float smw[39];
    int tid = threadIdx.x;
    int b = blockIdx.x >> 6;
    int p0 = (blockIdx.x & 63) * 32;
    int base = b * SDIFF;
    int dh = blockIdx.y * 256;        // half offset within row

    // stage 39 blended row-slices (uint4 = 8 halves) + mw taps (rows p0-8 .. p0+30, clamped)
    #pragma unroll
    for (int i = 0; i < 5; i++) {
        int q = tid + i * 256;
        if (q < 39 * 32) {
            int j = q >> 5, col = q & 31;
            int rr = p0 - 8 + j;
            int gr = base + (rr < 0 ? 0 : rr);
            uint4 v = ((const uint4*)d_blh)[((size_t)gr * DD + dh) / 8 + col];
            sm[j][2*col]   = make_uint2(v.x, v.y);
            sm[j][2*col+1] = make_uint2(v.z, v.w);
        }
    }
    if (tid < 39) {
        int rr = p0 - 8 + tid;
        smw[tid] = d_mw[base + (rr < 0 ? 0 : rr)];
    }
    __syncthreads();

    #pragma unroll
    for (int i = 0; i < 8; i++) {
        int item = i * 256 + tid;
        int pl = item >> 6, col = item & 63;
        int p = p0 + pl;
        float c[WW];
        float wsum = 0.f;
        #pragma unroll
        for (int k = 0; k < WW; k++) {
            int idx = p - WW + k;
            float ck = 0.f;
            if (p >= 1 && idx >= 0) {
                int w = (p < WW) ? p : WW;
                int j = k - (WW - w);
                float lin = (w > 1) ? (0.1f + 0.9f * (float)j / (float)(w - 1)) : 0.1f;
                ck = lin * smw[pl + k];
            }
            c[k] = ck;
            wsum += ck;
        }
        float inv = 1.0f / fmaxf(wsum, 1e-8f);
        float4 o = make_float4(0.f, 0.f, 0.f, 0.f);
        #pragma unroll
        for (int k = 0; k < WW; k++) {
            if (c[k] != 0.f) {
                uint2 u = sm[pl + k][col];
                float2 fa = __half22float2(*(__half2*)&u.x);
                float2 fb = __half22float2(*(__half2*)&u.y);
                o.x = fmaf(c[k], fa.x, o.x);
                o.y = fmaf(c[k], fa.y, o.y);
                o.z = fmaf(c[k], fb.x, o.z);
                o.w = fmaf(c[k], fb.y, o.w);
            }
        }
        o.x *= inv; o.y *= inv; o.z *= inv; o.w *= inv;
        ((float4*)out)[(size_t)(b * SS + p) * 256 + (dh >> 2) + col] = o;
    }
}

extern "C" void kernel_launch(void* const* d_in, const int* in_sizes, int n_in,
                              void* d_out, int out_size) {
    (void)in_sizes; (void)n_in; (void)out_size;
    const float* emb  = (const float*)d_in[0];
    const float* guid = (const float*)d_in[1];
    float* out = (float*)d_out;

    cudaFuncSetAttribute(k_mm1, cudaFuncAttributeMaxDynamicSharedMemorySize, SMEM1);
    cudaFuncSetAttribute(k_mm2, cudaFuncAttributeMaxDynamicSharedMemorySize, SMEM1);

    k_fused<<<2048, 256>>>(emb, guid);
    k_mm1<<<dim3(64, 2), 256, SMEM1>>>();
    k_mm2<<<dim3(64, 4), 256, SMEM1>>>();
    k_out<<<dim3(256, 4), 256>>>(out);
}

// round 14
// speedup vs baseline: 4.1098x; 1.0484x over previous
#include <cuda_runtime.h>
#include <cuda_fp16.h>
#include <mma.h>
#include <cstdint>
#include <math.h>

using namespace nvcuda;

#define BB 4
#define SS 2048
#define DD 1024
#define GG 512
#define WW 8
#define SDIFF 2047
#define ND (BB*SDIFF)            // 8188
#define MPAD 8192

// GEMMs: fp16, CTA 128m x 256n, 256 thr (8 warps, warp tile 64x64), K-chunk 64, 3-stage.
#define LDA1 72                  // fp16 elems (144B rows)
#define BUF1 55296               // 128*144 + 256*144
#define LDC1 260
#define SMEM1 165888             // 3*BUF1 (> epilogue 128*260*4=133120)

#define CP_ASYNC16(dst, src) \
    asm volatile("cp.async.cg.shared.global [%0], [%1], 16;" :: "r"(dst), "l"(src))
#define CP_COMMIT() asm volatile("cp.async.commit_group;" ::: "memory")
#define CP_WAIT1() asm volatile("cp.async.wait_group 1;" ::: "memory")
#define CP_WAIT0() asm volatile("cp.async.wait_group 0;" ::: "memory")

__device__ __forceinline__ uint32_t smem_u32(const void* p) {
    uint32_t a;
    asm("{ .reg .u64 t; cvta.to.shared.u64 t, %1; cvt.u32.u64 %0, t; }" : "=r"(a) : "l"(p));
    return a;
}

// ---------------- global scratch ----------------
__device__ __half  d_gh[GG * DD];              // guid/||g|| fp16 [g][k]
__device__ __half  d_gth[DD * GG];             // guid^T fp16 [d][g]
__device__ __half  d_nh[(size_t)MPAD * DD];    // normed fp16 [r][k]
__device__ float   d_mw[MPAD];                 // tanh(2*mag)
__device__ __half  d_wh[(size_t)MPAD * GG];    // exp(2*sims) fp16 [r][g]
__device__ float   d_sums[MPAD];               // row sums of exp (f32)
__device__ __half  d_blh[(size_t)MPAD * DD];   // blended fp16 [r][d]

// ---------------- fused prep: gprep (512) + gt (512) + diff-prep (1024) ----------------
__global__ void __launch_bounds__(256) k_fused(const float* __restrict__ emb,
                                               const float* __restrict__ guid) {
    int bid = blockIdx.x;
    int tid = threadIdx.x;
    if (bid < 512) {
        int g = bid;
        const float4* row = (const float4*)(guid + (size_t)g * DD);
        float4 x = row[tid];
        float s = x.x*x.x + x.y*x.y + x.z*x.z + x.w*x.w;
        #pragma unroll
        for (int o = 16; o; o >>= 1) s += __shfl_xor_sync(0xffffffffu, s, o);
        __shared__ float red[8];
        __shared__ float sinv;
        if ((tid & 31) == 0) red[tid >> 5] = s;
        __syncthreads();
        if (tid == 0) {
            float t = 0.f;
            #pragma unroll
            for (int i = 0; i < 8; i++) t += red[i];
            sinv = 1.0f / fmaxf(sqrtf(t), 1e-8f);
        }
        __syncthreads();
        float inv = sinv;
        __half2* o1 = (__half2*)(d_gh + (size_t)g * DD);
        o1[2*tid]   = __floats2half2_rn(x.x * inv, x.y * inv);
        o1[2*tid+1] = __floats2half2_rn(x.z * inv, x.w * inv);
    } else if (bid < 1024) {
        __shared__ float tile[32][33];
        int lb = bid - 512;
        int d0 = (lb & 31) * 32, g0 = (lb >> 5) * 32;
        int tx = tid & 31, ty = tid >> 5;
        #pragma unroll
        for (int yy = ty; yy < 32; yy += 8)
            tile[yy][tx] = guid[(size_t)(g0 + yy) * DD + (d0 + tx)];
        __syncthreads();
        #pragma unroll
        for (int yy = ty; yy < 32; yy += 8)
            d_gth[(size_t)(d0 + yy) * GG + (g0 + tx)] = __float2half_rn(tile[tx][yy]);
    } else {
        int lane = tid & 31, wid = tid >> 5;
        int r = (bid - 1024) * 8 + wid;
        if (lane == 0) d_sums[r] = 0.f;
        __half2* nb = (__half2*)(d_nh + (size_t)r * DD);
        if (r >= ND) {
            __half2 z = __floats2half2_rn(0.f, 0.f);
            #pragma unroll
            for (int it = 0; it < 8; it++) {
                int v = lane + 32 * it;
                nb[2*v] = z; nb[2*v+1] = z;
            }
            if (lane == 0) d_mw[r] = 0.f;
            return;
        }
        int b = r / SDIFF;
        int i = r - b * SDIFF;
        const float4* e0 = (const float4*)(emb + ((size_t)b * SS + i) * DD);
        float4 df[8];
        float ssq = 0.f;
        #pragma unroll
        for (int it = 0; it < 8; it++) {
            int v = lane + 32 * it;
            float4 a = e0[v + DD/4];
            float4 c = e0[v];
            df[it].x = a.x - c.x; df[it].y = a.y - c.y;
            df[it].z = a.z - c.z; df[it].w = a.w - c.w;
            ssq += df[it].x*df[it].x + df[it].y*df[it].y + df[it].z*df[it].z + df[it].w*df[it].w;
        }
        #pragma unroll
        for (int o = 16; o; o >>= 1) ssq += __shfl_xor_sync(0xffffffffu, ssq, o);
        float mag = sqrtf(ssq);
        float scale = (mag > 1e-6f) ? (1.0f / mag) : 0.0f;
        if (lane == 0) d_mw[r] = tanhf(2.0f * mag);
        #pragma unroll
        for (int it = 0; it < 8; it++) {
            int v = lane + 32 * it;
            nb[2*v]   = __floats2half2_rn(df[it].x * scale, df[it].y * scale);
            nb[2*v+1] = __floats2half2_rn(df[it].z * scale, df[it].w * scale);
        }
    }
}

// ---------------- mm1: sims = normed x gh^T (fp16) + exp epilogue ----------------
__global__ void __launch_bounds__(256, 1) k_mm1() {
    extern __shared__ __align__(128) char smem[];
    uint32_t sbase = smem_u32(smem);
    int tid = threadIdx.x, wid = tid >> 5;
    int wm = wid >> 2, wn = wid & 3;
    int m0 = blockIdx.x * 128, n0 = blockIdx.y * 256;

    wmma::fragment<wmma::accumulator, 16, 16, 16, float> acc[4][4];
    #pragma unroll
    for (int mi = 0; mi < 4; mi++)
        #pragma unroll
        for (int ni = 0; ni < 4; ni++)
            wmma::fill_fragment(acc[mi][ni], 0.0f);

    auto load_chunk = [&](int kc, int buf) {
        uint32_t ab = sbase + buf * BUF1;
        #pragma unroll
        for (int i = 0; i < 4; i++) {
            int q = tid + i * 256;
            int r = q >> 3, v = q & 7;
            const char* src = (const char*)d_nh + ((size_t)(m0 + r) * DD + kc * 64 + v * 8) * 2;
            CP_ASYNC16(ab + r * 144 + v * 16, src);
        }
        uint32_t bb = ab + 18432;
        #pragma unroll
        for (int i = 0; i < 8; i++) {
            int q = tid + i * 256;
            int r = q >> 3, v = q & 7;
            const char* src = (const char*)d_gh + ((size_t)(n0 + r) * DD + kc * 64 + v * 8) * 2;
            CP_ASYNC16(bb + r * 144 + v * 16, src);
        }
        CP_COMMIT();
    };

    load_chunk(0, 0);
    load_chunk(1, 1);
    for (int kc = 0; kc < 16; kc++) {
        CP_WAIT1();
        __syncthreads();
        if (kc + 2 < 16) load_chunk(kc + 2, (kc + 2) % 3);
        const __half* As = (const __half*)(smem + (kc % 3) * BUF1);
        const __half* Bs = As + 9216;
        #pragma unroll
        for (int ks = 0; ks < 4; ks++) {
            wmma::fragment<wmma::matrix_a, 16, 16, 16, __half, wmma::row_major> af[4];
            wmma::fragment<wmma::matrix_b, 16, 16, 16, __half, wmma::col_major> bf[4];
            #pragma unroll
            for (int mi = 0; mi < 4; mi++)
                wmma::load_matrix_sync(af[mi], As + (wm*64 + mi*16) * LDA1 + ks*16, LDA1);
            #pragma unroll
            for (int ni = 0; ni < 4; ni++)
                wmma::load_matrix_sync(bf[ni], Bs + (wn*64 + ni*16) * LDA1 + ks*16, LDA1);
            #pragma unroll
            for (int mi = 0; mi < 4; mi++)
                #pragma unroll
                for (int ni = 0; ni < 4; ni++)
                    wmma::mma_sync(acc[mi][ni], af[mi], bf[ni], acc[mi][ni]);
        }
    }
    CP_WAIT0();
    __syncthreads();
    float* Cs = (float*)smem;   // [128][LDC1]
    #pragma unroll
    for (int mi = 0; mi < 4; mi++)
        #pragma unroll
        for (int ni = 0; ni < 4; ni++)
            wmma::store_matrix_sync(Cs + (wm*64 + mi*16) * LDC1 + wn*64 + ni*16,
                                    acc[mi][ni], LDC1, wmma::mem_row_major);
    __syncthreads();

    int row = tid >> 1, c0 = (tid & 1) * 128;
    float sum = 0.f;
    __half2* wout = (__half2*)(d_wh + (size_t)(m0 + row) * GG + n0 + c0);
    #pragma unroll 8
    for (int j = 0; j < 128; j += 4) {
        float e0 = __expf(2.0f * Cs[row * LDC1 + c0 + j + 0]);
        float e1 = __expf(2.0f * Cs[row * LDC1 + c0 + j + 1]);
        float e2 = __expf(2.0f * Cs[row * LDC1 + c0 + j + 2]);
        float e3 = __expf(2.0f * Cs[row * LDC1 + c0 + j + 3]);
        sum += e0 + e1 + e2 + e3;
        wout[(j >> 1) + 0] = __floats2half2_rn(e0, e1);
        wout[(j >> 1) + 1] = __floats2half2_rn(e2, e3);
    }
    atomicAdd(&d_sums[m0 + row], sum);
}

// ---------------- mm2: influence = wh x gth^T (fp16) + blend epilogue (fp16 out) ----------------
__global__ void __launch_bounds__(256, 1) k_mm2() {
    extern __shared__ __align__(128) char smem[];
    uint32_t sbase = smem_u32(smem);
    int tid = threadIdx.x, wid = tid >> 5;
    int wm = wid >> 2, wn = wid & 3;
    int m0 = blockIdx.x * 128, n0 = blockIdx.y * 256;

    wmma::fragment<wmma::accumulator, 16, 16, 16, float> acc[4][4];
    #pragma unroll
    for (int mi = 0; mi < 4; mi++)
        #pragma unroll
        for (int ni = 0; ni < 4; ni++)
            wmma::fill_fragment(acc[mi][ni], 0.0f);

    auto load_chunk = [&](int kc, int buf) {
        uint32_t ab = sbase + buf * BUF1;
        #pragma unroll
        for (int i = 0; i < 4; i++) {
            int q = tid + i * 256;
            int r = q >> 3, v = q & 7;
            const char* src = (const char*)d_wh + ((size_t)(m0 + r) * GG + kc * 64 + v * 8) * 2;
            CP_ASYNC16(ab + r * 144 + v * 16, src);
        }
        uint32_t bb = ab + 18432;
        #pragma unroll
        for (int i = 0; i < 8; i++) {
            int q = tid + i * 256;
            int r = q >> 3, v = q & 7;
            const char* src = (const char*)d_gth + ((size_t)(n0 + r) * GG + kc * 64 + v * 8) * 2;
            CP_ASYNC16(bb + r * 144 + v * 16, src);
        }
        CP_COMMIT();
    };

    load_chunk(0, 0);
    load_chunk(1, 1);
    for (int kc = 0; kc < 8; kc++) {
        CP_WAIT1();
        __syncthreads();
        if (kc + 2 < 8) load_chunk(kc + 2, (kc + 2) % 3);
        const __half* As = (const __half*)(smem + (kc % 3) * BUF1);
        const __half* Bs = As + 9216;
        #pragma unroll
        for (int ks = 0; ks < 4; ks++) {
            wmma::fragment<wmma::matrix_a, 16, 16, 16, __half, wmma::row_major> af[4];
            wmma::fragment<wmma::matrix_b, 16, 16, 16, __half, wmma::col_major> bf[4];
            #pragma unroll
            for (int mi = 0; mi < 4; mi++)
                wmma::load_matrix_sync(af[mi], As + (wm*64 + mi*16) * LDA1 + ks*16, LDA1);
            #pragma unroll
            for (int ni = 0; ni < 4; ni++)
                wmma::load_matrix_sync(bf[ni], Bs + (wn*64 + ni*16) * LDA1 + ks*16, LDA1);
            #pragma unroll
            for (int mi = 0; mi < 4; mi++)
                #pragma unroll
                for (int ni = 0; ni < 4; ni++)
                    wmma::mma_sync(acc[mi][ni], af[mi], bf[ni], acc[mi][ni]);
        }
    }
    CP_WAIT0();
    __syncthreads();
    float* Cs = (float*)smem;   // [128][LDC1]
    #pragma unroll
    for (int mi = 0; mi < 4; mi++)
        #pragma unroll
        for (int ni = 0; ni < 4; ni++)
            wmma::store_matrix_sync(Cs + (wm*64 + mi*16) * LDC1 + wn*64 + ni*16,
                                    acc[mi][ni], LDC1, wmma::mem_row_major);
    __syncthreads();

    int row = tid >> 1, c0 = (tid & 1) * 128;
    int r = m0 + row;
    if (r < ND) {
        float sc = 0.4f / d_sums[r];
        const __half2* nh2 = (const __half2*)(d_nh + (size_t)r * DD + n0 + c0);
        uint2* ob = (uint2*)(d_blh + (size_t)r * DD + n0 + c0);
        #pragma unroll 8
        for (int j = 0; j < 32; j++) {
            float4 c = *(const float4*)&Cs[row * LDC1 + c0 + j * 4];
            float2 f0 = __half22float2(nh2[2*j]);
            float2 f1 = __half22float2(nh2[2*j+1]);
            __half2 h0 = __floats2half2_rn(0.6f * f0.x + sc * c.x, 0.6f * f0.y + sc * c.y);
            __half2 h1 = __floats2half2_rn(0.6f * f1.x + sc * c.z, 0.6f * f1.y + sc * c.w);
            uint2 u;
            u.x = *(uint32_t*)&h0;
            u.y = *(uint32_t*)&h1;
            ob[j] = u;
        }
    }
}

// ---------------- windowed weighted blend into output (fp16 smem, precomputed weights) ----------------
// grid (256, 4): x = 32-position group (4 batches x 64 groups), y = 256-elem d-slice.
__global__ void __launch_bounds__(256) k_out(float* __restrict__ out) {
    __shared__ uint2 sm[39][64];      // 39 rows x 256 halves
    __shared__ float smw[39];
    __shared__ float smc[32][WW];     // per-row tap weights
    __shared__ float sminv[32];       // per-row 1/wsum
    int tid = threadIdx.x;
    int b = blockIdx.x >> 6;
    int p0 = (blockIdx.x & 63) * 32;
    int base = b * SDIFF;
    int dh = blockIdx.y * 256;        // half offset within row

    // stage 39 blended row-slices + mw taps (rows p0-8 .. p0+30, clamped)
    #pragma unroll
    for (int i = 0; i < 5; i++) {
        int q = tid + i * 256;
        if (q < 39 * 32) {
            int j = q >> 5, col = q & 31;
            int rr = p0 - 8 + j;
            int gr = base + (rr < 0 ? 0 : rr);
            uint4 v = ((const uint4*)d_blh)[((size_t)gr * DD + dh) / 8 + col];
            sm[j][2*col]   = make_uint2(v.x, v.y);
            sm[j][2*col+1] = make_uint2(v.z, v.w);
        }
    }
    if (tid < 39) {
        int rr = p0 - 8 + tid;
        smw[tid] = d_mw[base + (rr < 0 ? 0 : rr)];
    }
    __syncthreads();

    // phase 0b: per-row weights (256 threads cover 32 rows x 8 taps)
    {
        int pl = tid >> 3, k = tid & 7;
        int p = p0 + pl;
        int idx = p - WW + k;
        float ck = 0.f;
        if (p >= 1 && idx >= 0) {
            int w = (p < WW) ? p : WW;
            int j = k - (WW - w);
            float lin = (w > 1) ? (0.1f + 0.9f * (float)j / (float)(w - 1)) : 0.1f;
            ck = lin * smw[pl + k];
        }
        smc[pl][k] = ck;
    }
    __syncthreads();
    if (tid < 32) {
        float ws = 0.f;
        #pragma unroll
        for (int k = 0; k < WW; k++) ws += smc[tid][k];
        sminv[tid] = 1.0f / fmaxf(ws, 1e-8f);
    }
    __syncthreads();

    #pragma unroll
    for (int i = 0; i < 8; i++) {
        int item = i * 256 + tid;
        int pl = item >> 6, col = item & 63;
        int p = p0 + pl;
        float inv = sminv[pl];
        float4 o = make_float4(0.f, 0.f, 0.f, 0.f);
        #pragma unroll
        for (int k = 0; k < WW; k++) {
            float ck = smc[pl][k];
            uint2 u = sm[pl + k][col];
            float2 fa = __half22float2(*(__half2*)&u.x);
            float2 fb = __half22float2(*(__half2*)&u.y);
            o.x = fmaf(ck, fa.x, o.x);
            o.y = fmaf(ck, fa.y, o.y);
            o.z = fmaf(ck, fb.x, o.z);
            o.w = fmaf(ck, fb.y, o.w);
        }
        o.x *= inv; o.y *= inv; o.z *= inv; o.w *= inv;
        ((float4*)out)[(size_t)(b * SS + p) * 256 + (dh >> 2) + col] = o;
    }
}

extern "C" void kernel_launch(void* const* d_in, const int* in_sizes, int n_in,
                              void* d_out, int out_size) {
    (void)in_sizes; (void)n_in; (void)out_size;
    const float* emb  = (const float*)d_in[0];
    const float* guid = (const float*)d_in[1];
    float* out = (float*)d_out;

    cudaFuncSetAttribute(k_mm1, cudaFuncAttributeMaxDynamicSharedMemorySize, SMEM1);
    cudaFuncSetAttribute(k_mm2, cudaFuncAttributeMaxDynamicSharedMemorySize, SMEM1);

    k_fused<<<2048, 256>>>(emb, guid);
    k_mm1<<<dim3(64, 2), 256, SMEM1>>>();
    k_mm2<<<dim3(64, 4), 256, SMEM1>>>();
    k_out<<<dim3(256, 4), 256>>>(out);
}